// round 4
// baseline (speedup 1.0000x reference)
#include <cuda_runtime.h>

// LDM Kalman forward: 256 sequences x 1024 sequential steps.
// One CTA (256 threads) per sequence. Woodbury form:
//   Lam_t = inv(inv(P) + C^T R^-1 C),  K = Lam_t C^T R^-1
// Steady-state freeze + post-freeze split (warp0: register mu recursion with
// software-pipelined loads; warps 1..7: stream frozen Lambda tiles).

#define T_STEPS 1024
#define NB 256
#define DX 16
#define DA 32

#define BASE_MP 0ul
#define BASE_MT 4194304ul
#define BASE_LP 8388608ul
#define BASE_LT 75497472ul

__device__ __forceinline__ float frcp_acc(float x) {
    float r;
    asm("rcp.approx.f32 %0, %1;" : "=f"(r) : "f"(x));
    float e = __fmaf_rn(-x, r, 1.0f);
    r = __fmaf_rn(r, e, r);
    return r;
}

// In-place Gauss-Jordan inverse of a 16x16 SPD matrix in shared memory.
// One element per thread (tid = i*16+j). One __syncthreads per pivot stage.
__device__ __forceinline__ void gj16(float (*M)[17], float (*rb)[DX],
                                     float (*cb)[DX], float* spv,
                                     int i, int j) {
    #pragma unroll
    for (int k = 0; k < DX; ++k) {
        const int par = k & 1, nx = par ^ 1;
        const float pr = frcp_acc(spv[par]);
        const float rk = rb[par][j];
        const float ck = cb[par][i];
        const float v  = M[i][j];
        float nv;
        if (i == k)      nv = (j == k) ? pr : rk * pr;
        else if (j == k) nv = -ck * pr;
        else             nv = __fmaf_rn(-(ck * pr), rk, v);
        M[i][j] = nv;
        if (k < DX - 1) {
            if (i == k + 1) rb[nx][j] = nv;
            if (j == k + 1) cb[nx][i] = nv;
            if (i == k + 1 && j == k + 1) spv[nx] = nv;
        }
        __syncthreads();
    }
}

__global__ __launch_bounds__(256, 2)
void ldm_kernel(const float* __restrict__ ga,   // [NB][T][DA]
                const float* __restrict__ gu,   // [NB][T][DX]
                const float* __restrict__ gmask,// [NB][T][1]
                const float* __restrict__ gA,
                const float* __restrict__ gB,
                const float* __restrict__ gC,
                const float* __restrict__ gmu0,
                const float* __restrict__ gLam0,
                const float* __restrict__ gWlog,
                const float* __restrict__ gRlog,
                float* __restrict__ out) {
    __shared__ float sA[DX][17], sB[DX][17], sCtRinvC[DX][17];
    __shared__ float sC[DA][17];
    __shared__ float sCtRinv[DX][33], sK[DX][33], sAK[DX][33];
    __shared__ float sM[DX][17], sT[DX][17], sLt[DX][17], sKC[DX][17];
    __shared__ float sP[2][DX][17];
    __shared__ float rb[2][DX], cb[2][DX], spv[2];
    __shared__ float s_rinv[DA], sW[DX];
    __shared__ float s_mu[DX], s_mut[DX], s_r[DA], s_u[DX];
    __shared__ __align__(16) float sPflat[256];
    __shared__ __align__(16) float sLtflat[256];
    __shared__ float s_mask[T_STEPS];
    __shared__ int sFlag;

    const int tid = threadIdx.x;
    const int i = tid >> 4, j = tid & 15;
    const int b = blockIdx.x;

    // ---------------- constants + mask preload ----------------
    sA[i][j] = gA[tid];
    sB[i][j] = gB[tid];
    for (int idx = tid; idx < DA * DX; idx += 256) sC[idx >> 4][idx & 15] = gC[idx];
    if (tid < DA) s_rinv[tid] = __expf(-gRlog[tid]);
    if (tid < DX) { sW[tid] = __expf(gWlog[tid]); s_mu[tid] = gmu0[tid]; }
    sP[0][i][j] = gLam0[tid];
    #pragma unroll
    for (int rep = 0; rep < T_STEPS / 256; ++rep)
        s_mask[tid + rep * 256] = gmask[(size_t)b * T_STEPS + tid + rep * 256];
    __syncthreads();
    for (int idx = tid; idx < DX * DA; idx += 256) {
        int x = idx >> 5, aa = idx & 31;
        sCtRinv[x][aa] = sC[aa][x] * s_rinv[aa];
    }
    __syncthreads();
    {
        float acc = 0.f;
        #pragma unroll
        for (int aa = 0; aa < DA; ++aa) acc = fmaf(sCtRinv[i][aa], sC[aa][j], acc);
        sCtRinvC[i][j] = acc;
    }
    __syncthreads();

    int cur = 0;
    int t_frozen = T_STEPS;

    // ---------------- main recursion (pre-freeze) ----------------
    for (int t = 0; t < T_STEPS; ++t) {
        if (tid == 0) sFlag = 0;
        const float m = s_mask[t];
        const bool m1 = (m == 1.0f);

        // prefetch this step's data early; consumed ~2 GJ inversions later
        float rga = 0.f, rgu = 0.f;
        if (tid < DA) {
            rga = __ldg(&ga[((size_t)b * T_STEPS + t) * DA + tid]);
        } else if (tid < DA + DX) {
            rgu = (t == T_STEPS - 1) ? 0.f
                : __ldg(&gu[((size_t)b * T_STEPS + t) * DX + (tid - DA)]);
        }

        {
            float v = sP[cur][i][j];
            sM[i][j] = v;
            if (i == 0) rb[0][j] = v;
            if (j == 0) cb[0][i] = v;
            if (tid == 0) spv[0] = v;
        }
        __syncthreads();
        gj16(sM, rb, cb, spv, i, j);                 // sM = P^-1

        {
            float nv = sM[i][j] + sCtRinvC[i][j];
            sM[i][j] = nv;
            if (i == 0) rb[0][j] = nv;
            if (j == 0) cb[0][i] = nv;
            if (tid == 0) spv[0] = nv;
        }
        __syncthreads();
        gj16(sM, rb, cb, spv, i, j);                 // sM = Lam_t

        {
            #pragma unroll
            for (int rep = 0; rep < 2; ++rep) {
                int idx = tid + rep * 256;
                int ri = idx >> 5, ca = idx & 31;
                float acc = 0.f;
                #pragma unroll
                for (int y = 0; y < DX; ++y) acc = fmaf(sM[ri][y], sCtRinv[y][ca], acc);
                sK[ri][ca] = acc;
            }
            float acc = 0.f;
            #pragma unroll
            for (int k = 0; k < DX; ++k) acc = fmaf(sA[i][k], sM[k][j], acc);
            sT[i][j] = acc;
            if (m1) sLt[i][j] = sM[i][j];
        }
        __syncthreads();
        if (!m1) {  // general-mask path: Lt = P - m*(K C)P ; T1 = A@Lt
            float acc = 0.f;
            #pragma unroll
            for (int aa = 0; aa < DA; ++aa) acc = fmaf(sK[i][aa], sC[aa][j], acc);
            sKC[i][j] = acc;
            __syncthreads();
            float acc2 = 0.f;
            #pragma unroll
            for (int k = 0; k < DX; ++k) acc2 = fmaf(sKC[i][k], sP[cur][k][j], acc2);
            sLt[i][j] = sP[cur][i][j] - m * acc2;
            __syncthreads();
            float acc3 = 0.f;
            #pragma unroll
            for (int k = 0; k < DX; ++k) acc3 = fmaf(sA[i][k], sLt[k][j], acc3);
            sT[i][j] = acc3;
            __syncthreads();
        }

        const int nxt = cur ^ 1;
        {
            float acc = (i == j) ? sW[i] : 0.f;
            #pragma unroll
            for (int k = 0; k < DX; ++k) acc = fmaf(sT[i][k], sA[j][k], acc);
            sP[nxt][i][j] = acc;
            if (fabsf(acc - sP[cur][i][j]) > 1e-6f) sFlag = 1;
            size_t off = ((size_t)t * NB + b) * 256 + tid;
            out[BASE_LP + off] = acc;
            out[BASE_LT + off] = sLt[i][j];
            if (tid < DA) {
                float ap = 0.f;
                #pragma unroll
                for (int k = 0; k < DX; ++k) ap = fmaf(sC[tid][k], s_mu[k], ap);
                s_r[tid] = fmaf(m, rga, -ap);
            } else if (tid < DA + DX) {
                s_u[tid - DA] = rgu;
            }
        }
        __syncthreads();
        if (tid < DX) {
            float acc = 0.f;
            #pragma unroll
            for (int aa = 0; aa < DA; ++aa) acc = fmaf(sK[tid][aa], s_r[aa], acc);
            float mt = s_mu[tid] + m * acc;
            s_mut[tid] = mt;
            out[BASE_MT + ((size_t)t * NB + b) * DX + tid] = mt;
        }
        __syncthreads();
        if (tid < DX) {
            float acc = 0.f;
            #pragma unroll
            for (int k = 0; k < DX; ++k) acc = fmaf(sA[tid][k], s_mut[k], acc);
            #pragma unroll
            for (int k = 0; k < DX; ++k) acc = fmaf(sB[tid][k], s_u[k], acc);
            s_mu[tid] = acc;
            out[BASE_MP + ((size_t)t * NB + b) * DX + tid] = acc;
        }
        const bool conv = m1 && (sFlag == 0);
        __syncthreads();
        cur = nxt;
        if (conv) { t_frozen = t; break; }
    }

    // ---------------- post-freeze fast path ----------------
    if (t_frozen < T_STEPS - 1) {
        sPflat[tid]  = sP[cur][i][j];
        sLtflat[tid] = sLt[i][j];
        // AK = A @ K (frozen), computed once by all 256 threads
        #pragma unroll
        for (int rep = 0; rep < 2; ++rep) {
            int idx = tid + rep * 256;
            int ri = idx >> 5, ca = idx & 31;
            float acc = 0.f;
            #pragma unroll
            for (int y = 0; y < DX; ++y) acc = fmaf(sA[ri][y], sK[y][ca], acc);
            sAK[ri][ca] = acc;
        }
        __syncthreads();
        const int warp = tid >> 5, lane = tid & 31;
        const int t0 = t_frozen + 1;
        if (warp == 0) {
            const int lr = lane & 15;
            float Crow[DX], Krow[DA], AKrow[DA];
            #pragma unroll
            for (int k = 0; k < DX; ++k) Crow[k] = sC[lane][k];
            #pragma unroll
            for (int aa = 0; aa < DA; ++aa) Krow[aa] = sK[lr][aa];
            #pragma unroll
            for (int aa = 0; aa < DA; ++aa) AKrow[aa] = sAK[lr][aa];
            float mu = s_mu[lr];

            auto ldA = [&](int tt) -> float {
                return (tt < T_STEPS)
                    ? __ldg(&ga[((size_t)b * T_STEPS + tt) * DA + lane]) : 0.f;
            };
            auto ldU = [&](int tt) -> float {
                return (lane < DX && tt < T_STEPS - 1)
                    ? __ldg(&gu[((size_t)b * T_STEPS + tt) * DX + lane]) : 0.f;
            };
            auto doStep = [&](int t, float av, float uv) {
                const float m = s_mask[t];
                float cm0 = 0.f, cm1 = 0.f, z = 0.f;
                #pragma unroll
                for (int k = 0; k < DX; k += 2) {
                    float m0 = __shfl_sync(0xffffffffu, mu, k);
                    float m1 = __shfl_sync(0xffffffffu, mu, k + 1);
                    cm0 = fmaf(Crow[k], m0, cm0);
                    cm1 = fmaf(Crow[k + 1], m1, cm1);
                    z = fmaf(sA[lr][k], m0, z);
                    z = fmaf(sA[lr][k + 1], m1, z);
                }
                float r = fmaf(m, av, -(cm0 + cm1));
                float kk0 = 0.f, kk1 = 0.f, ak0 = 0.f, ak1 = 0.f;
                #pragma unroll
                for (int aa = 0; aa < DA; aa += 2) {
                    float r0 = __shfl_sync(0xffffffffu, r, aa);
                    float r1 = __shfl_sync(0xffffffffu, r, aa + 1);
                    kk0 = fmaf(Krow[aa], r0, kk0);
                    ak0 = fmaf(AKrow[aa], r0, ak0);
                    kk1 = fmaf(Krow[aa + 1], r1, kk1);
                    ak1 = fmaf(AKrow[aa + 1], r1, ak1);
                }
                float mt = fmaf(m, kk0 + kk1, mu);
                float bu = 0.f;
                #pragma unroll
                for (int k = 0; k < DX; ++k)
                    bu = fmaf(sB[lr][k], __shfl_sync(0xffffffffu, uv, k), bu);
                float mun = z + fmaf(m, ak0 + ak1, bu);
                if (lane < DX) {
                    out[BASE_MT + ((size_t)t * NB + b) * DX + lane] = mt;
                    out[BASE_MP + ((size_t)t * NB + b) * DX + lane] = mun;
                }
                if (t + 12 < T_STEPS) {  // DRAM->L2 prefetch, zero reg cost
                    asm volatile("prefetch.global.L2 [%0];" ::
                        "l"(&ga[((size_t)b * T_STEPS + t + 12) * DA + lane]));
                    if (lane < DX)
                        asm volatile("prefetch.global.L2 [%0];" ::
                            "l"(&gu[((size_t)b * T_STEPS + t + 12) * DX + lane]));
                }
                mu = mun;
            };

            int t = t0;
            float pa0 = ldA(t),     pu0 = ldU(t);
            float pa1 = ldA(t + 1), pu1 = ldU(t + 1);
            float pa2 = ldA(t + 2), pu2 = ldU(t + 2);
            float pa3 = ldA(t + 3), pu3 = ldU(t + 3);
            for (; t + 3 < T_STEPS; t += 4) {
                doStep(t, pa0, pu0);     pa0 = ldA(t + 4); pu0 = ldU(t + 4);
                doStep(t + 1, pa1, pu1); pa1 = ldA(t + 5); pu1 = ldU(t + 5);
                doStep(t + 2, pa2, pu2); pa2 = ldA(t + 6); pu2 = ldU(t + 6);
                doStep(t + 3, pa3, pu3); pa3 = ldA(t + 7); pu3 = ldU(t + 7);
            }
            if (t < T_STEPS)     doStep(t, pa0, pu0);
            if (t + 1 < T_STEPS) doStep(t + 1, pa1, pu1);
            if (t + 2 < T_STEPS) doStep(t + 2, pa2, pu2);
        } else {
            // warps 1..7: stream frozen Lambda tiles (pure STG bandwidth)
            const float4* pf = (const float4*)sPflat;
            const float4* lf = (const float4*)sLtflat;
            float4 p0 = pf[2 * lane], p1 = pf[2 * lane + 1];
            float4 l0 = lf[2 * lane], l1 = lf[2 * lane + 1];
            for (int tt = t0 + (warp - 1); tt < T_STEPS; tt += 7) {
                size_t off = ((size_t)tt * NB + b) * 256 + lane * 8;
                float4* o1 = (float4*)(out + BASE_LP + off);
                o1[0] = p0; o1[1] = p1;
                float4* o2 = (float4*)(out + BASE_LT + off);
                o2[0] = l0; o2[1] = l1;
            }
        }
    }
}

extern "C" void kernel_launch(void* const* d_in, const int* in_sizes, int n_in,
                              void* d_out, int out_size) {
    (void)in_sizes; (void)n_in; (void)out_size;
    ldm_kernel<<<NB, 256>>>(
        (const float*)d_in[0], (const float*)d_in[1], (const float*)d_in[2],
        (const float*)d_in[3], (const float*)d_in[4], (const float*)d_in[5],
        (const float*)d_in[6], (const float*)d_in[7], (const float*)d_in[8],
        (const float*)d_in[9], (float*)d_out);
}

// round 6
// speedup vs baseline: 3.0543x; 3.0543x over previous
#include <cuda_runtime.h>

// LDM Kalman forward: 256 sequences x 1024 sequential steps.
// One CTA (256 threads) per sequence. Woodbury info form:
//   Lam_t = inv(inv(P) + C^T R^-1 C),  K = Lam_t C^T R^-1
// 2x2-block Gauss-Jordan (8 barrier stages per 16x16 inverse).
// Steady-state freeze; post-freeze the mu recursion is chunked across all 8
// warps using burn-in (closed-loop M = A(I-KC) is strongly contracting), and
// all 8 warps stream the frozen Lambda tiles interleaved with the mu chunks.

#define T_STEPS 1024
#define NB 256
#define DX 16
#define DA 32

#define BASE_MP 0ul
#define BASE_MT 4194304ul
#define BASE_LP 8388608ul
#define BASE_LT 75497472ul

__device__ __forceinline__ float frcp_acc(float x) {
    float r;
    asm("rcp.approx.f32 %0, %1;" : "=f"(r) : "f"(x));
    float e = __fmaf_rn(-x, r, 1.0f);
    r = __fmaf_rn(r, e, r);
    return r;
}

// In-place 2x2-block Gauss-Jordan inverse of a 16x16 SPD matrix in shared
// memory. One element per thread (tid = i*16+j). 8 pivot stages, one
// __syncthreads each; threads owning the NEXT stage's rows/cols publish new
// values into ping-pong buffers within the same stage.
__device__ __forceinline__ void gj16b(float (*M)[17], float (*rb)[2][DX],
                                      float (*cb)[2][DX], float (*spv)[4],
                                      int i, int j) {
    #pragma unroll
    for (int s = 0; s < 8; ++s) {
        const int par = s & 1, nx = par ^ 1;
        const int k0 = 2 * s, k1 = 2 * s + 1;
        const float p00 = spv[par][0], p01 = spv[par][1];
        const float p10 = spv[par][2], p11 = spv[par][3];
        const float rd = frcp_acc(__fmaf_rn(p00, p11, -(p01 * p10)));
        const float q00 = p11 * rd, q01 = -p01 * rd;
        const float q10 = -p10 * rd, q11 = p00 * rd;
        const float r0 = rb[par][0][j], r1 = rb[par][1][j]; // old M[k0][j],M[k1][j]
        const float c0 = cb[par][0][i], c1 = cb[par][1][i]; // old M[i][k0],M[i][k1]
        const float v = M[i][j];
        const float w0 = __fmaf_rn(q00, r0, q01 * r1);
        const float w1 = __fmaf_rn(q10, r0, q11 * r1);
        const bool ip = (i == k0) || (i == k1);
        const bool jp = (j == k0) || (j == k1);
        float nv;
        if (ip && jp)      nv = (i == k0) ? ((j == k0) ? q00 : q01)
                                          : ((j == k0) ? q10 : q11);
        else if (ip)       nv = (i == k0) ? w0 : w1;
        else if (jp)       nv = (j == k0) ? -__fmaf_rn(c0, q00, c1 * q10)
                                          : -__fmaf_rn(c0, q01, c1 * q11);
        else               nv = v - __fmaf_rn(c0, w0, c1 * w1);
        M[i][j] = nv;
        if (s < 7) {
            if (i == k0 + 2) rb[nx][0][j] = nv;
            if (i == k0 + 3) rb[nx][1][j] = nv;
            if (j == k0 + 2) cb[nx][0][i] = nv;
            if (j == k0 + 3) cb[nx][1][i] = nv;
            if ((i == k0 + 2 || i == k0 + 3) && (j == k0 + 2 || j == k0 + 3))
                spv[nx][(i - k0 - 2) * 2 + (j - k0 - 2)] = nv;
        }
        __syncthreads();
    }
}

__global__ __launch_bounds__(256, 2)
void ldm_kernel(const float* __restrict__ ga,   // [NB][T][DA]
                const float* __restrict__ gu,   // [NB][T][DX]
                const float* __restrict__ gmask,// [NB][T][1]
                const float* __restrict__ gA,
                const float* __restrict__ gB,
                const float* __restrict__ gC,
                const float* __restrict__ gmu0,
                const float* __restrict__ gLam0,
                const float* __restrict__ gWlog,
                const float* __restrict__ gRlog,
                float* __restrict__ out) {
    __shared__ float sA[DX][17], sB[DX][17], sCtRinvC[DX][17];
    __shared__ float sC[DA][17];
    __shared__ float sCtRinv[DX][33], sK[DX][33];
    __shared__ float sM[DX][17], sT[DX][17], sLt[DX][17], sKC[DX][17];
    __shared__ float sP[2][DX][17];
    __shared__ float rb[2][2][DX], cb[2][2][DX], spv[2][4];
    __shared__ float s_rinv[DA], sW[DX];
    __shared__ float s_mu[DX], s_mut[DX], s_r[DA], s_u[DX];
    __shared__ __align__(16) float sPflat[256];
    __shared__ __align__(16) float sLtflat[256];
    __shared__ float s_mask[T_STEPS];
    __shared__ int sFlag;
    __shared__ int sLastMasked;

    const int tid = threadIdx.x;
    const int i = tid >> 4, j = tid & 15;
    const int b = blockIdx.x;

    // ---------------- constants + mask preload ----------------
    if (tid == 0) sLastMasked = -1;
    __syncthreads();
    sA[i][j] = gA[tid];
    sB[i][j] = gB[tid];
    for (int idx = tid; idx < DA * DX; idx += 256) sC[idx >> 4][idx & 15] = gC[idx];
    if (tid < DA) s_rinv[tid] = __expf(-gRlog[tid]);
    if (tid < DX) { sW[tid] = __expf(gWlog[tid]); s_mu[tid] = gmu0[tid]; }
    sP[0][i][j] = gLam0[tid];
    #pragma unroll
    for (int rep = 0; rep < T_STEPS / 256; ++rep) {
        int idx = tid + rep * 256;
        float mv = gmask[(size_t)b * T_STEPS + idx];
        s_mask[idx] = mv;
        if (mv != 1.0f) atomicMax(&sLastMasked, idx);
    }
    __syncthreads();
    for (int idx = tid; idx < DX * DA; idx += 256) {
        int x = idx >> 5, aa = idx & 31;
        sCtRinv[x][aa] = sC[aa][x] * s_rinv[aa];
    }
    __syncthreads();
    {
        float acc = 0.f;
        #pragma unroll
        for (int aa = 0; aa < DA; ++aa) acc = fmaf(sCtRinv[i][aa], sC[aa][j], acc);
        sCtRinvC[i][j] = acc;
    }
    __syncthreads();

    int cur = 0;
    int t_frozen = T_STEPS;
    const int lastMasked = sLastMasked;

    // ---------------- main recursion (pre-freeze) ----------------
    for (int t = 0; t < T_STEPS; ++t) {
        if (tid == 0) sFlag = 0;
        const float m = s_mask[t];
        const bool m1 = (m == 1.0f);

        // issue this step's data loads early; consumed ~2 inversions later
        float rga = 0.f, rgu = 0.f;
        if (tid < DA) {
            rga = __ldg(&ga[((size_t)b * T_STEPS + t) * DA + tid]);
        } else if (tid < DA + DX) {
            rgu = (t == T_STEPS - 1) ? 0.f
                : __ldg(&gu[((size_t)b * T_STEPS + t) * DX + (tid - DA)]);
        }

        {
            float v = sP[cur][i][j];
            sM[i][j] = v;
            if (i < 2) rb[0][i][j] = v;
            if (j < 2) cb[0][j][i] = v;
            if (i < 2 && j < 2) spv[0][i * 2 + j] = v;
        }
        __syncthreads();
        gj16b(sM, rb, cb, spv, i, j);                // sM = P^-1

        {
            float nv = sM[i][j] + sCtRinvC[i][j];
            sM[i][j] = nv;
            if (i < 2) rb[0][i][j] = nv;
            if (j < 2) cb[0][j][i] = nv;
            if (i < 2 && j < 2) spv[0][i * 2 + j] = nv;
        }
        __syncthreads();
        gj16b(sM, rb, cb, spv, i, j);                // sM = Lam_t

        {
            #pragma unroll
            for (int rep = 0; rep < 2; ++rep) {
                int idx = tid + rep * 256;
                int ri = idx >> 5, ca = idx & 31;
                float acc = 0.f;
                #pragma unroll
                for (int y = 0; y < DX; ++y) acc = fmaf(sM[ri][y], sCtRinv[y][ca], acc);
                sK[ri][ca] = acc;
            }
            float acc = 0.f;
            #pragma unroll
            for (int k = 0; k < DX; ++k) acc = fmaf(sA[i][k], sM[k][j], acc);
            sT[i][j] = acc;
            if (m1) sLt[i][j] = sM[i][j];
        }
        __syncthreads();
        if (!m1) {  // exact general-mask path: Lt = P - m*(K C)P ; T1 = A@Lt
            float acc = 0.f;
            #pragma unroll
            for (int aa = 0; aa < DA; ++aa) acc = fmaf(sK[i][aa], sC[aa][j], acc);
            sKC[i][j] = acc;
            __syncthreads();
            float acc2 = 0.f;
            #pragma unroll
            for (int k = 0; k < DX; ++k) acc2 = fmaf(sKC[i][k], sP[cur][k][j], acc2);
            sLt[i][j] = sP[cur][i][j] - m * acc2;
            __syncthreads();
            float acc3 = 0.f;
            #pragma unroll
            for (int k = 0; k < DX; ++k) acc3 = fmaf(sA[i][k], sLt[k][j], acc3);
            sT[i][j] = acc3;
            __syncthreads();
        }

        const int nxt = cur ^ 1;
        {
            float acc = (i == j) ? sW[i] : 0.f;
            #pragma unroll
            for (int k = 0; k < DX; ++k) acc = fmaf(sT[i][k], sA[j][k], acc);
            sP[nxt][i][j] = acc;
            if (fabsf(acc - sP[cur][i][j]) > 1e-6f) sFlag = 1;
            size_t off = ((size_t)t * NB + b) * 256 + tid;
            out[BASE_LP + off] = acc;
            out[BASE_LT + off] = sLt[i][j];
            if (tid < DA) {
                float ap = 0.f;
                #pragma unroll
                for (int k = 0; k < DX; ++k) ap = fmaf(sC[tid][k], s_mu[k], ap);
                s_r[tid] = fmaf(m, rga, -ap);
            } else if (tid < DA + DX) {
                s_u[tid - DA] = rgu;
            }
        }
        __syncthreads();
        if (tid < DX) {
            float acc = 0.f;
            #pragma unroll
            for (int aa = 0; aa < DA; ++aa) acc = fmaf(sK[tid][aa], s_r[aa], acc);
            float mt = s_mu[tid] + m * acc;
            s_mut[tid] = mt;
            out[BASE_MT + ((size_t)t * NB + b) * DX + tid] = mt;
        }
        __syncthreads();
        if (tid < DX) {
            float acc = 0.f;
            #pragma unroll
            for (int k = 0; k < DX; ++k) acc = fmaf(sA[tid][k], s_mut[k], acc);
            #pragma unroll
            for (int k = 0; k < DX; ++k) acc = fmaf(sB[tid][k], s_u[k], acc);
            s_mu[tid] = acc;
            out[BASE_MP + ((size_t)t * NB + b) * DX + tid] = acc;
        }
        // freeze only if converged AND no masked step remains downstream
        const bool conv = m1 && (sFlag == 0) && (t >= lastMasked);
        __syncthreads();
        cur = nxt;
        if (conv) { t_frozen = t; break; }
    }

    // ---------------- post-freeze: chunked mu + 8-warp Lambda stream -------
    if (t_frozen < T_STEPS) {
        sPflat[tid]  = sP[cur][i][j];   // frozen Lam_pred
        sLtflat[tid] = sLt[i][j];       // frozen Lam_t
        __syncthreads();

        const int warp = tid >> 5, lane = tid & 31, lr = lane & 15;
        const int t0f = t_frozen + 1;
        const int n = T_STEPS - t0f;
        const int L = (n + 7) / 8;
        const int cs = t0f + warp * L;                       // chunk start
        const int ce = min(cs + L, T_STEPS);                 // chunk end
        const int tb = (warp == 0) ? t0f : cs - L;           // burn-in start

        // frozen Lambda tiles in registers for streaming
        const float4* pf = (const float4*)sPflat;
        const float4* lf = (const float4*)sLtflat;
        const float4 p0 = pf[2 * lane], p1 = pf[2 * lane + 1];
        const float4 l0 = lf[2 * lane], l1 = lf[2 * lane + 1];
        int tt = t0f + warp;   // this warp's Lambda write cursor (stride 8)

        float Crow[DX], Krow[DA];
        #pragma unroll
        for (int k = 0; k < DX; ++k) Crow[k] = sC[lane][k];
        #pragma unroll
        for (int aa = 0; aa < DA; ++aa) Krow[aa] = sK[lr][aa];

        float mu = (warp == 0) ? s_mu[lr] : 0.f;   // burn-in warps start at 0

        for (int t = tb; t < ce; ++t) {
            const float m = s_mask[t];
            const float av = __ldg(&ga[((size_t)b * T_STEPS + t) * DA + lane]);
            const float uv = (lane < DX && t < T_STEPS - 1)
                ? __ldg(&gu[((size_t)b * T_STEPS + t) * DX + lane]) : 0.f;
            // interleaved Lambda streaming (fire-and-forget stores)
            if (tt < T_STEPS) {
                size_t off = ((size_t)tt * NB + b) * 256 + lane * 8;
                float4* o1 = (float4*)(out + BASE_LP + off);
                o1[0] = p0; o1[1] = p1;
                float4* o2 = (float4*)(out + BASE_LT + off);
                o2[0] = l0; o2[1] = l1;
                tt += 8;
            }
            // mu recursion step
            float ap0 = 0.f, ap1 = 0.f;
            #pragma unroll
            for (int k = 0; k < DX; k += 2) {
                ap0 = fmaf(Crow[k],     __shfl_sync(0xffffffffu, mu, k),     ap0);
                ap1 = fmaf(Crow[k + 1], __shfl_sync(0xffffffffu, mu, k + 1), ap1);
            }
            const float r = fmaf(m, av, -(ap0 + ap1));
            float g0 = 0.f, g1 = 0.f, g2 = 0.f, g3 = 0.f;
            #pragma unroll
            for (int aa = 0; aa < DA; aa += 4) {
                g0 = fmaf(Krow[aa],     __shfl_sync(0xffffffffu, r, aa),     g0);
                g1 = fmaf(Krow[aa + 1], __shfl_sync(0xffffffffu, r, aa + 1), g1);
                g2 = fmaf(Krow[aa + 2], __shfl_sync(0xffffffffu, r, aa + 2), g2);
                g3 = fmaf(Krow[aa + 3], __shfl_sync(0xffffffffu, r, aa + 3), g3);
            }
            const float mt = fmaf(m, (g0 + g1) + (g2 + g3), mu);
            float mun = 0.f;
            #pragma unroll
            for (int k = 0; k < DX; ++k) {
                mun = fmaf(sA[lr][k], __shfl_sync(0xffffffffu, mt, k), mun);
                mun = fmaf(sB[lr][k], __shfl_sync(0xffffffffu, uv, k), mun);
            }
            if (t >= cs && lane < DX) {
                out[BASE_MT + ((size_t)t * NB + b) * DX + lane] = mt;
                out[BASE_MP + ((size_t)t * NB + b) * DX + lane] = mun;
            }
            mu = mun;
        }
        // cleanup: any remaining Lambda writes for this warp
        for (; tt < T_STEPS; tt += 8) {
            size_t off = ((size_t)tt * NB + b) * 256 + lane * 8;
            float4* o1 = (float4*)(out + BASE_LP + off);
            o1[0] = p0; o1[1] = p1;
            float4* o2 = (float4*)(out + BASE_LT + off);
            o2[0] = l0; o2[1] = l1;
        }
    }
}

extern "C" void kernel_launch(void* const* d_in, const int* in_sizes, int n_in,
                              void* d_out, int out_size) {
    (void)in_sizes; (void)n_in; (void)out_size;
    ldm_kernel<<<NB, 256>>>(
        (const float*)d_in[0], (const float*)d_in[1], (const float*)d_in[2],
        (const float*)d_in[3], (const float*)d_in[4], (const float*)d_in[5],
        (const float*)d_in[6], (const float*)d_in[7], (const float*)d_in[8],
        (const float*)d_in[9], (float*)d_out);
}

// round 7
// speedup vs baseline: 4.3758x; 1.4327x over previous
#include <cuda_runtime.h>

// LDM Kalman forward, 256 seq x 1024 steps, restructured as 6 launches:
//   k_init   : reset flags
//   k_scan   : verify mask==1 everywhere (else fallback kernel does all work)
//   k1       : shared Riccati recursion to steady state (1 CTA), stores
//              per-step M_t=A(I-K_tC), G_t=I-K_tC, N_t=AK_t, K_t, Lambdas
//   k2       : per (b,t): d=N a+B u, f=K a into scratch; stream all Lambda out
//   k3       : chunked affine mu recursion (burn-in), 16 shfl+16 FMA per step
//   fallback : full general-mask kernel (guarded; runs only if scan fails)

#define T_STEPS 1024
#define NB 256
#define DX 16
#define DA 32
#define TC 192   // Riccati step cap

#define BASE_MP 0ul
#define BASE_MT 4194304ul
#define BASE_LP 8388608ul
#define BASE_LT 75497472ul

__device__ int g_allones;
__device__ int g_tc;
__device__ float g_Mt[TC][DX][17];
__device__ float g_Gt[TC][DX][17];
__device__ float g_Nt[TC][DX][33];
__device__ float g_Kt[TC][DX][33];
__device__ float g_Lp[TC][256];
__device__ float g_Lt[TC][256];
__device__ float g_df[2][NB][T_STEPS][DX];   // [0]=d, [1]=f

__device__ __forceinline__ float frcp_acc(float x) {
    float r;
    asm("rcp.approx.f32 %0, %1;" : "=f"(r) : "f"(x));
    float e = __fmaf_rn(-x, r, 1.0f);
    r = __fmaf_rn(r, e, r);
    return r;
}

// In-place 2x2-block Gauss-Jordan inverse of 16x16 SPD matrix in smem.
__device__ __forceinline__ void gj16b(float (*M)[17], float (*rb)[2][DX],
                                      float (*cb)[2][DX], float (*spv)[4],
                                      int i, int j) {
    #pragma unroll
    for (int s = 0; s < 8; ++s) {
        const int par = s & 1, nx = par ^ 1;
        const int k0 = 2 * s, k1 = 2 * s + 1;
        const float p00 = spv[par][0], p01 = spv[par][1];
        const float p10 = spv[par][2], p11 = spv[par][3];
        const float rd = frcp_acc(__fmaf_rn(p00, p11, -(p01 * p10)));
        const float q00 = p11 * rd, q01 = -p01 * rd;
        const float q10 = -p10 * rd, q11 = p00 * rd;
        const float r0 = rb[par][0][j], r1 = rb[par][1][j];
        const float c0 = cb[par][0][i], c1 = cb[par][1][i];
        const float v = M[i][j];
        const float w0 = __fmaf_rn(q00, r0, q01 * r1);
        const float w1 = __fmaf_rn(q10, r0, q11 * r1);
        const bool ip = (i == k0) || (i == k1);
        const bool jp = (j == k0) || (j == k1);
        float nv;
        if (ip && jp)      nv = (i == k0) ? ((j == k0) ? q00 : q01)
                                          : ((j == k0) ? q10 : q11);
        else if (ip)       nv = (i == k0) ? w0 : w1;
        else if (jp)       nv = (j == k0) ? -__fmaf_rn(c0, q00, c1 * q10)
                                          : -__fmaf_rn(c0, q01, c1 * q11);
        else               nv = v - __fmaf_rn(c0, w0, c1 * w1);
        M[i][j] = nv;
        if (s < 7) {
            if (i == k0 + 2) rb[nx][0][j] = nv;
            if (i == k0 + 3) rb[nx][1][j] = nv;
            if (j == k0 + 2) cb[nx][0][i] = nv;
            if (j == k0 + 3) cb[nx][1][i] = nv;
            if ((i == k0 + 2 || i == k0 + 3) && (j == k0 + 2 || j == k0 + 3))
                spv[nx][(i - k0 - 2) * 2 + (j - k0 - 2)] = nv;
        }
        __syncthreads();
    }
}

__global__ void k_init() { g_allones = 1; g_tc = 0; }

__global__ void k_scan(const float* __restrict__ gmask) {
    int idx = blockIdx.x * 256 + threadIdx.x;
    if (gmask[idx] != 1.0f) atomicAnd(&g_allones, 0);
}

// ---------------- K1: shared Riccati to steady state (1 CTA) ----------------
__global__ __launch_bounds__(256, 1)
void k1_riccati(const float* __restrict__ gA, const float* __restrict__ gC,
                const float* __restrict__ gLam0, const float* __restrict__ gWlog,
                const float* __restrict__ gRlog) {
    if (!g_allones) return;
    __shared__ float sA[DX][17], sCtRinvC[DX][17], sC[DA][17];
    __shared__ float sCtRinv[DX][33], sK[DX][33];
    __shared__ float sM[DX][17], sT[DX][17], sG[DX][17];
    __shared__ float sP[2][DX][17];
    __shared__ float rb[2][2][DX], cb[2][2][DX], spv[2][4];
    __shared__ float s_rinv[DA], sW[DX];
    __shared__ int sFlag;

    const int tid = threadIdx.x;
    const int i = tid >> 4, j = tid & 15;

    sA[i][j] = gA[tid];
    for (int idx = tid; idx < DA * DX; idx += 256) sC[idx >> 4][idx & 15] = gC[idx];
    if (tid < DA) s_rinv[tid] = __expf(-gRlog[tid]);
    if (tid < DX) sW[tid] = __expf(gWlog[tid]);
    sP[0][i][j] = gLam0[tid];
    __syncthreads();
    for (int idx = tid; idx < DX * DA; idx += 256) {
        int x = idx >> 5, aa = idx & 31;
        sCtRinv[x][aa] = sC[aa][x] * s_rinv[aa];
    }
    __syncthreads();
    {
        float acc = 0.f;
        #pragma unroll
        for (int aa = 0; aa < DA; ++aa) acc = fmaf(sCtRinv[i][aa], sC[aa][j], acc);
        sCtRinvC[i][j] = acc;
    }
    __syncthreads();

    int cur = 0, tcv = -1;
    for (int t = 0; t < TC; ++t) {
        if (tid == 0) sFlag = 0;
        {
            float v = sP[cur][i][j];
            sM[i][j] = v;
            if (i < 2) rb[0][i][j] = v;
            if (j < 2) cb[0][j][i] = v;
            if (i < 2 && j < 2) spv[0][i * 2 + j] = v;
        }
        __syncthreads();
        gj16b(sM, rb, cb, spv, i, j);                // P^-1
        {
            float nv = sM[i][j] + sCtRinvC[i][j];
            sM[i][j] = nv;
            if (i < 2) rb[0][i][j] = nv;
            if (j < 2) cb[0][j][i] = nv;
            if (i < 2 && j < 2) spv[0][i * 2 + j] = nv;
        }
        __syncthreads();
        gj16b(sM, rb, cb, spv, i, j);                // Lam_t
        {
            #pragma unroll
            for (int rep = 0; rep < 2; ++rep) {
                int idx = tid + rep * 256;
                int ri = idx >> 5, ca = idx & 31;
                float acc = 0.f;
                #pragma unroll
                for (int y = 0; y < DX; ++y) acc = fmaf(sM[ri][y], sCtRinv[y][ca], acc);
                sK[ri][ca] = acc;
            }
            float acc = 0.f;
            #pragma unroll
            for (int k = 0; k < DX; ++k) acc = fmaf(sA[i][k], sM[k][j], acc);
            sT[i][j] = acc;                           // A @ Lam_t
            g_Lt[t][tid] = sM[i][j];
        }
        __syncthreads();
        {   // G = I - K C
            float kc = 0.f;
            #pragma unroll
            for (int aa = 0; aa < DA; ++aa) kc = fmaf(sK[i][aa], sC[aa][j], kc);
            sG[i][j] = ((i == j) ? 1.f : 0.f) - kc;
            #pragma unroll
            for (int rep = 0; rep < 2; ++rep) {       // store K
                int idx = tid + rep * 256;
                int ri = idx >> 5, ca = idx & 31;
                g_Kt[t][ri][ca] = sK[ri][ca];
            }
        }
        __syncthreads();
        const int nxt = cur ^ 1;
        {
            float mm = 0.f;
            #pragma unroll
            for (int k = 0; k < DX; ++k) mm = fmaf(sA[i][k], sG[k][j], mm);
            g_Mt[t][i][j] = mm;
            g_Gt[t][i][j] = sG[i][j];
            #pragma unroll
            for (int rep = 0; rep < 2; ++rep) {       // N = A K
                int idx = tid + rep * 256;
                int ri = idx >> 5, ca = idx & 31;
                float acc = 0.f;
                #pragma unroll
                for (int y = 0; y < DX; ++y) acc = fmaf(sA[ri][y], sK[y][ca], acc);
                g_Nt[t][ri][ca] = acc;
            }
            float pn = (i == j) ? sW[i] : 0.f;
            #pragma unroll
            for (int k = 0; k < DX; ++k) pn = fmaf(sT[i][k], sA[j][k], pn);
            g_Lp[t][tid] = pn;
            if (fabsf(pn - sP[cur][i][j]) > 1e-6f) sFlag = 1;
            sP[nxt][i][j] = pn;
        }
        __syncthreads();
        const int fl = sFlag;
        __syncthreads();
        cur = nxt;
        if (!fl) { tcv = t; break; }
    }
    if (tid == 0) {
        if (tcv < 0) g_allones = 0;   // did not converge: fallback handles all
        else g_tc = tcv;
    }
}

// ---------------- K2: d/f precompute + Lambda streaming ----------------
__global__ __launch_bounds__(256, 4)
void k2_dfl(const float* __restrict__ ga, const float* __restrict__ gu,
            const float* __restrict__ gB, float* __restrict__ out) {
    if (!g_allones) return;
    const int tc = g_tc;
    const int b = blockIdx.x >> 6;
    const int t0 = (blockIdx.x & 63) << 4;
    const int tid = threadIdx.x;

    __shared__ float s_a[16][32], s_u[16][16];
    __shared__ float cN[DX][33], cK[DX][33], cB[DX][17];
    __shared__ __align__(16) float sLp[256], sLt[256];

    s_a[tid >> 5][tid & 31] = ga[((size_t)b * T_STEPS + t0) * DA + tid];
    {
        int q = tid + 256;
        s_a[q >> 5][q & 31] = ga[((size_t)b * T_STEPS + t0) * DA + q];
    }
    s_u[tid >> 4][tid & 15] = gu[((size_t)b * T_STEPS + t0) * DX + tid];
    for (int idx = tid; idx < DX * 33; idx += 256) {
        ((float*)cN)[idx] = ((const float*)g_Nt[tc])[idx];
        ((float*)cK)[idx] = ((const float*)g_Kt[tc])[idx];
    }
    cB[tid >> 4][tid & 15] = gB[tid];
    sLp[tid] = g_Lp[tc][tid];
    sLt[tid] = g_Lt[tc][tid];
    __syncthreads();

    const int i = tid & 15, task = tid >> 4;
    const int t = t0 + task;
    float d = 0.f, f = 0.f;
    if (t >= tc) {
        #pragma unroll
        for (int aa = 0; aa < DA; ++aa) {
            float av = s_a[task][aa];
            d = fmaf(cN[i][aa], av, d);
            f = fmaf(cK[i][aa], av, f);
        }
    } else {
        #pragma unroll
        for (int aa = 0; aa < DA; ++aa) {
            float av = s_a[task][aa];
            d = fmaf(__ldg(&g_Nt[t][i][aa]), av, d);
            f = fmaf(__ldg(&g_Kt[t][i][aa]), av, f);
        }
    }
    if (t != T_STEPS - 1) {
        #pragma unroll
        for (int k = 0; k < DX; ++k) d = fmaf(cB[i][k], s_u[task][k], d);
    }
    g_df[0][b][t][i] = d;
    g_df[1][b][t][i] = f;

    // Lambda streaming: 16 tasks x 64 float4 per array
    #pragma unroll
    for (int rep = 0; rep < 4; ++rep) {
        int q = tid + rep * 256;
        int task2 = q >> 6, e4 = q & 63;
        int tt = t0 + task2;
        float4 vp, vl;
        if (tt >= tc) {
            vp = ((const float4*)sLp)[e4];
            vl = ((const float4*)sLt)[e4];
        } else {
            vp = ((const float4*)g_Lp[tt])[e4];
            vl = ((const float4*)g_Lt[tt])[e4];
        }
        size_t off = ((size_t)tt * NB + b) * 256 + (size_t)e4 * 4;
        *(float4*)(out + BASE_LP + off) = vp;
        *(float4*)(out + BASE_LT + off) = vl;
    }
}

// ---------------- K3: chunked affine mu recursion ----------------
__global__ __launch_bounds__(256, 2)
void k3_mu(const float* __restrict__ gmu0, float* __restrict__ out) {
    if (!g_allones) return;
    const int tc = g_tc;
    const int b = blockIdx.x;
    const int warp = threadIdx.x >> 5, lane = threadIdx.x & 31, r = lane & 15;
    const int cs = warp * 128, ce = cs + 128;
    const int s = (warp == 0) ? 0 : cs - 64;   // 64-step burn-in

    float cst[16];
    {
        const float (*CF)[17] = (lane < 16) ? g_Mt[tc] : g_Gt[tc];
        #pragma unroll
        for (int k = 0; k < DX; ++k) cst[k] = CF[r][k];
    }
    const float* dfb = (lane < 16) ? &g_df[0][b][0][r] : &g_df[1][b][0][r];
    float mu = (warp == 0 && lane < 16) ? __ldg(&gmu0[r]) : 0.f;

    auto ld = [&](int t) { return __ldg(dfb + (size_t)t * DX); };
    auto body = [&](int t, const float* cf, float val) {
        float a0 = 0.f, a1 = 0.f, a2 = 0.f, a3 = 0.f;
        #pragma unroll
        for (int k = 0; k < DX; k += 4) {
            a0 = fmaf(cf[k],     __shfl_sync(0xffffffffu, mu, k),     a0);
            a1 = fmaf(cf[k + 1], __shfl_sync(0xffffffffu, mu, k + 1), a1);
            a2 = fmaf(cf[k + 2], __shfl_sync(0xffffffffu, mu, k + 2), a2);
            a3 = fmaf(cf[k + 3], __shfl_sync(0xffffffffu, mu, k + 3), a3);
        }
        float res = ((a0 + a1) + (a2 + a3)) + val;
        if (t >= cs)
            out[((lane < 16) ? BASE_MP : BASE_MT) + ((size_t)t * NB + b) * DX + r] = res;
        mu = res;
    };
    auto dostep = [&](int t, float val) {
        if (t < tc) {
            float cf[16];
            const float (*CF)[17] = (lane < 16) ? g_Mt[t] : g_Gt[t];
            #pragma unroll
            for (int k = 0; k < DX; ++k) cf[k] = __ldg(&CF[r][k]);
            body(t, cf, val);
        } else {
            body(t, cst, val);
        }
    };

    int t = s;
    float v0 = ld(t), v1 = ld(t + 1), v2 = ld(t + 2), v3 = ld(t + 3);
    for (; t < ce; t += 4) {
        dostep(t, v0);     v0 = (t + 4 < ce) ? ld(t + 4) : 0.f;
        dostep(t + 1, v1); v1 = (t + 5 < ce) ? ld(t + 5) : 0.f;
        dostep(t + 2, v2); v2 = (t + 6 < ce) ? ld(t + 6) : 0.f;
        dostep(t + 3, v3); v3 = (t + 7 < ce) ? ld(t + 7) : 0.f;
    }
}

// ---------------- Fallback: full general-mask kernel (R5, guarded) ----------
__global__ __launch_bounds__(256, 2)
void ldm_fallback(const float* __restrict__ ga, const float* __restrict__ gu,
                  const float* __restrict__ gmask, const float* __restrict__ gA,
                  const float* __restrict__ gB, const float* __restrict__ gC,
                  const float* __restrict__ gmu0, const float* __restrict__ gLam0,
                  const float* __restrict__ gWlog, const float* __restrict__ gRlog,
                  float* __restrict__ out) {
    if (g_allones) return;
    __shared__ float sA[DX][17], sB[DX][17], sCtRinvC[DX][17];
    __shared__ float sC[DA][17];
    __shared__ float sCtRinv[DX][33], sK[DX][33];
    __shared__ float sM[DX][17], sT[DX][17], sLt[DX][17], sKC[DX][17];
    __shared__ float sP[2][DX][17];
    __shared__ float rb[2][2][DX], cb[2][2][DX], spv[2][4];
    __shared__ float s_rinv[DA], sW[DX];
    __shared__ float s_mu[DX], s_mut[DX], s_r[DA], s_u[DX];
    __shared__ __align__(16) float sPflat[256];
    __shared__ __align__(16) float sLtflat[256];
    __shared__ float s_mask[T_STEPS];
    __shared__ int sFlag;
    __shared__ int sLastMasked;

    const int tid = threadIdx.x;
    const int i = tid >> 4, j = tid & 15;
    const int b = blockIdx.x;

    if (tid == 0) sLastMasked = -1;
    __syncthreads();
    sA[i][j] = gA[tid];
    sB[i][j] = gB[tid];
    for (int idx = tid; idx < DA * DX; idx += 256) sC[idx >> 4][idx & 15] = gC[idx];
    if (tid < DA) s_rinv[tid] = __expf(-gRlog[tid]);
    if (tid < DX) { sW[tid] = __expf(gWlog[tid]); s_mu[tid] = gmu0[tid]; }
    sP[0][i][j] = gLam0[tid];
    #pragma unroll
    for (int rep = 0; rep < T_STEPS / 256; ++rep) {
        int idx = tid + rep * 256;
        float mv = gmask[(size_t)b * T_STEPS + idx];
        s_mask[idx] = mv;
        if (mv != 1.0f) atomicMax(&sLastMasked, idx);
    }
    __syncthreads();
    for (int idx = tid; idx < DX * DA; idx += 256) {
        int x = idx >> 5, aa = idx & 31;
        sCtRinv[x][aa] = sC[aa][x] * s_rinv[aa];
    }
    __syncthreads();
    {
        float acc = 0.f;
        #pragma unroll
        for (int aa = 0; aa < DA; ++aa) acc = fmaf(sCtRinv[i][aa], sC[aa][j], acc);
        sCtRinvC[i][j] = acc;
    }
    __syncthreads();

    int cur = 0;
    int t_frozen = T_STEPS;
    const int lastMasked = sLastMasked;

    for (int t = 0; t < T_STEPS; ++t) {
        if (tid == 0) sFlag = 0;
        const float m = s_mask[t];
        const bool m1 = (m == 1.0f);
        float rga = 0.f, rgu = 0.f;
        if (tid < DA) {
            rga = __ldg(&ga[((size_t)b * T_STEPS + t) * DA + tid]);
        } else if (tid < DA + DX) {
            rgu = (t == T_STEPS - 1) ? 0.f
                : __ldg(&gu[((size_t)b * T_STEPS + t) * DX + (tid - DA)]);
        }
        {
            float v = sP[cur][i][j];
            sM[i][j] = v;
            if (i < 2) rb[0][i][j] = v;
            if (j < 2) cb[0][j][i] = v;
            if (i < 2 && j < 2) spv[0][i * 2 + j] = v;
        }
        __syncthreads();
        gj16b(sM, rb, cb, spv, i, j);
        {
            float nv = sM[i][j] + sCtRinvC[i][j];
            sM[i][j] = nv;
            if (i < 2) rb[0][i][j] = nv;
            if (j < 2) cb[0][j][i] = nv;
            if (i < 2 && j < 2) spv[0][i * 2 + j] = nv;
        }
        __syncthreads();
        gj16b(sM, rb, cb, spv, i, j);
        {
            #pragma unroll
            for (int rep = 0; rep < 2; ++rep) {
                int idx = tid + rep * 256;
                int ri = idx >> 5, ca = idx & 31;
                float acc = 0.f;
                #pragma unroll
                for (int y = 0; y < DX; ++y) acc = fmaf(sM[ri][y], sCtRinv[y][ca], acc);
                sK[ri][ca] = acc;
            }
            float acc = 0.f;
            #pragma unroll
            for (int k = 0; k < DX; ++k) acc = fmaf(sA[i][k], sM[k][j], acc);
            sT[i][j] = acc;
            if (m1) sLt[i][j] = sM[i][j];
        }
        __syncthreads();
        if (!m1) {
            float acc = 0.f;
            #pragma unroll
            for (int aa = 0; aa < DA; ++aa) acc = fmaf(sK[i][aa], sC[aa][j], acc);
            sKC[i][j] = acc;
            __syncthreads();
            float acc2 = 0.f;
            #pragma unroll
            for (int k = 0; k < DX; ++k) acc2 = fmaf(sKC[i][k], sP[cur][k][j], acc2);
            sLt[i][j] = sP[cur][i][j] - m * acc2;
            __syncthreads();
            float acc3 = 0.f;
            #pragma unroll
            for (int k = 0; k < DX; ++k) acc3 = fmaf(sA[i][k], sLt[k][j], acc3);
            sT[i][j] = acc3;
            __syncthreads();
        }
        const int nxt = cur ^ 1;
        {
            float acc = (i == j) ? sW[i] : 0.f;
            #pragma unroll
            for (int k = 0; k < DX; ++k) acc = fmaf(sT[i][k], sA[j][k], acc);
            sP[nxt][i][j] = acc;
            if (fabsf(acc - sP[cur][i][j]) > 1e-6f) sFlag = 1;
            size_t off = ((size_t)t * NB + b) * 256 + tid;
            out[BASE_LP + off] = acc;
            out[BASE_LT + off] = sLt[i][j];
            if (tid < DA) {
                float ap = 0.f;
                #pragma unroll
                for (int k = 0; k < DX; ++k) ap = fmaf(sC[tid][k], s_mu[k], ap);
                s_r[tid] = fmaf(m, rga, -ap);
            } else if (tid < DA + DX) {
                s_u[tid - DA] = rgu;
            }
        }
        __syncthreads();
        if (tid < DX) {
            float acc = 0.f;
            #pragma unroll
            for (int aa = 0; aa < DA; ++aa) acc = fmaf(sK[tid][aa], s_r[aa], acc);
            float mt = s_mu[tid] + m * acc;
            s_mut[tid] = mt;
            out[BASE_MT + ((size_t)t * NB + b) * DX + tid] = mt;
        }
        __syncthreads();
        if (tid < DX) {
            float acc = 0.f;
            #pragma unroll
            for (int k = 0; k < DX; ++k) acc = fmaf(sA[tid][k], s_mut[k], acc);
            #pragma unroll
            for (int k = 0; k < DX; ++k) acc = fmaf(sB[tid][k], s_u[k], acc);
            s_mu[tid] = acc;
            out[BASE_MP + ((size_t)t * NB + b) * DX + tid] = acc;
        }
        const bool conv = m1 && (sFlag == 0) && (t >= lastMasked);
        __syncthreads();
        cur = nxt;
        if (conv) { t_frozen = t; break; }
    }

    if (t_frozen < T_STEPS) {
        sPflat[tid]  = sP[cur][i][j];
        sLtflat[tid] = sLt[i][j];
        __syncthreads();
        const int warp = tid >> 5, lane = tid & 31, lr = lane & 15;
        const int t0f = t_frozen + 1;
        const int n = T_STEPS - t0f;
        const int L = (n + 7) / 8;
        const int cs = t0f + warp * L;
        const int ce = min(cs + L, T_STEPS);
        const int tb = (warp == 0) ? t0f : cs - L;
        const float4* pf = (const float4*)sPflat;
        const float4* lf = (const float4*)sLtflat;
        const float4 p0 = pf[2 * lane], p1 = pf[2 * lane + 1];
        const float4 l0 = lf[2 * lane], l1 = lf[2 * lane + 1];
        int tt = t0f + warp;
        float Crow[DX], Krow[DA];
        #pragma unroll
        for (int k = 0; k < DX; ++k) Crow[k] = sC[lane][k];
        #pragma unroll
        for (int aa = 0; aa < DA; ++aa) Krow[aa] = sK[lr][aa];
        float mu = (warp == 0) ? s_mu[lr] : 0.f;
        for (int t = tb; t < ce; ++t) {
            const float m = s_mask[t];
            const float av = __ldg(&ga[((size_t)b * T_STEPS + t) * DA + lane]);
            const float uv = (lane < DX && t < T_STEPS - 1)
                ? __ldg(&gu[((size_t)b * T_STEPS + t) * DX + lane]) : 0.f;
            if (tt < T_STEPS) {
                size_t off = ((size_t)tt * NB + b) * 256 + lane * 8;
                float4* o1 = (float4*)(out + BASE_LP + off);
                o1[0] = p0; o1[1] = p1;
                float4* o2 = (float4*)(out + BASE_LT + off);
                o2[0] = l0; o2[1] = l1;
                tt += 8;
            }
            float ap0 = 0.f, ap1 = 0.f;
            #pragma unroll
            for (int k = 0; k < DX; k += 2) {
                ap0 = fmaf(Crow[k],     __shfl_sync(0xffffffffu, mu, k),     ap0);
                ap1 = fmaf(Crow[k + 1], __shfl_sync(0xffffffffu, mu, k + 1), ap1);
            }
            const float r = fmaf(m, av, -(ap0 + ap1));
            float g0 = 0.f, g1 = 0.f, g2 = 0.f, g3 = 0.f;
            #pragma unroll
            for (int aa = 0; aa < DA; aa += 4) {
                g0 = fmaf(Krow[aa],     __shfl_sync(0xffffffffu, r, aa),     g0);
                g1 = fmaf(Krow[aa + 1], __shfl_sync(0xffffffffu, r, aa + 1), g1);
                g2 = fmaf(Krow[aa + 2], __shfl_sync(0xffffffffu, r, aa + 2), g2);
                g3 = fmaf(Krow[aa + 3], __shfl_sync(0xffffffffu, r, aa + 3), g3);
            }
            const float mt = fmaf(m, (g0 + g1) + (g2 + g3), mu);
            float mun = 0.f;
            #pragma unroll
            for (int k = 0; k < DX; ++k) {
                mun = fmaf(sA[lr][k], __shfl_sync(0xffffffffu, mt, k), mun);
                mun = fmaf(sB[lr][k], __shfl_sync(0xffffffffu, uv, k), mun);
            }
            if (t >= cs && lane < DX) {
                out[BASE_MT + ((size_t)t * NB + b) * DX + lane] = mt;
                out[BASE_MP + ((size_t)t * NB + b) * DX + lane] = mun;
            }
            mu = mun;
        }
        for (; tt < T_STEPS; tt += 8) {
            size_t off = ((size_t)tt * NB + b) * 256 + lane * 8;
            float4* o1 = (float4*)(out + BASE_LP + off);
            o1[0] = p0; o1[1] = p1;
            float4* o2 = (float4*)(out + BASE_LT + off);
            o2[0] = l0; o2[1] = l1;
        }
    }
}

extern "C" void kernel_launch(void* const* d_in, const int* in_sizes, int n_in,
                              void* d_out, int out_size) {
    (void)in_sizes; (void)n_in; (void)out_size;
    const float* ga    = (const float*)d_in[0];
    const float* gu    = (const float*)d_in[1];
    const float* gmask = (const float*)d_in[2];
    const float* gA    = (const float*)d_in[3];
    const float* gB    = (const float*)d_in[4];
    const float* gC    = (const float*)d_in[5];
    const float* gmu0  = (const float*)d_in[6];
    const float* gLam0 = (const float*)d_in[7];
    const float* gWlog = (const float*)d_in[8];
    const float* gRlog = (const float*)d_in[9];
    float* out = (float*)d_out;

    k_init<<<1, 1>>>();
    k_scan<<<(NB * T_STEPS) / 256, 256>>>(gmask);
    k1_riccati<<<1, 256>>>(gA, gC, gLam0, gWlog, gRlog);
    k2_dfl<<<NB * 64, 256>>>(ga, gu, gB, out);
    k3_mu<<<NB, 256>>>(gmu0, out);
    ldm_fallback<<<NB, 256>>>(ga, gu, gmask, gA, gB, gC, gmu0, gLam0,
                              gWlog, gRlog, out);
}

// round 8
// speedup vs baseline: 4.5803x; 1.0467x over previous
#include <cuda_runtime.h>

// LDM Kalman forward, 256 seq x 1024 steps, 6 launches:
//   k_init, k_scan  : flags + mask==1 verification
//   k1_riccati      : shared Riccati to steady state (1 CTA), stores per-step
//                     M_t=A(I-K_tC), G_t=I-K_tC, N_t=AK_t, K_t, Lambdas
//   k2_dfl          : 64 t/CTA; steady N/K/B halves in registers; d=N a+B u,
//                     f=K a; streams all Lambda outputs with __stcs
//   k3_mu           : chunked affine mu recursion (burn-in), 16 shfl+16 FMA/step
//   ldm_fallback    : full general-mask kernel (guarded)

#define T_STEPS 1024
#define NB 256
#define DX 16
#define DA 32
#define TC 192

#define BASE_MP 0ul
#define BASE_MT 4194304ul
#define BASE_LP 8388608ul
#define BASE_LT 75497472ul

__device__ int g_allones;
__device__ int g_tc;
__device__ float g_Mt[TC][DX][17];
__device__ float g_Gt[TC][DX][17];
__device__ float g_Nt[TC][DX][33];
__device__ float g_Kt[TC][DX][33];
__device__ __align__(16) float g_Lp[TC][256];
__device__ __align__(16) float g_Lt[TC][256];
__device__ float g_df[2][NB][T_STEPS][DX];

__device__ __forceinline__ float frcp_acc(float x) {
    float r;
    asm("rcp.approx.f32 %0, %1;" : "=f"(r) : "f"(x));
    float e = __fmaf_rn(-x, r, 1.0f);
    r = __fmaf_rn(r, e, r);
    return r;
}

// 2x2-block Gauss-Jordan stage body (shared by both variants)
__device__ __forceinline__ float gj_stage(float (*M)[17], float (*rb)[2][DX],
                                          float (*cb)[2][DX], float (*spv)[4],
                                          int i, int j, int s) {
    const int par = s & 1;
    const int k0 = 2 * s, k1 = 2 * s + 1;
    const float p00 = spv[par][0], p01 = spv[par][1];
    const float p10 = spv[par][2], p11 = spv[par][3];
    const float rd = frcp_acc(__fmaf_rn(p00, p11, -(p01 * p10)));
    const float q00 = p11 * rd, q01 = -p01 * rd;
    const float q10 = -p10 * rd, q11 = p00 * rd;
    const float r0 = rb[par][0][j], r1 = rb[par][1][j];
    const float c0 = cb[par][0][i], c1 = cb[par][1][i];
    const float v = M[i][j];
    const float w0 = __fmaf_rn(q00, r0, q01 * r1);
    const float w1 = __fmaf_rn(q10, r0, q11 * r1);
    const bool ip = (i == k0) || (i == k1);
    const bool jp = (j == k0) || (j == k1);
    float nv;
    if (ip && jp)      nv = (i == k0) ? ((j == k0) ? q00 : q01)
                                      : ((j == k0) ? q10 : q11);
    else if (ip)       nv = (i == k0) ? w0 : w1;
    else if (jp)       nv = (j == k0) ? -__fmaf_rn(c0, q00, c1 * q10)
                                      : -__fmaf_rn(c0, q01, c1 * q11);
    else               nv = v - __fmaf_rn(c0, w0, c1 * w1);
    return nv;
}

// plain variant: publishes next-stage buffers at s<7 (as in fallback)
__device__ __forceinline__ void gj16b(float (*M)[17], float (*rb)[2][DX],
                                      float (*cb)[2][DX], float (*spv)[4],
                                      int i, int j) {
    #pragma unroll
    for (int s = 0; s < 8; ++s) {
        const int nx = (s & 1) ^ 1;
        const int k0 = 2 * s;
        float nv = gj_stage(M, rb, cb, spv, i, j, s);
        M[i][j] = nv;
        if (s < 7) {
            if (i == k0 + 2) rb[nx][0][j] = nv;
            if (i == k0 + 3) rb[nx][1][j] = nv;
            if (j == k0 + 2) cb[nx][0][i] = nv;
            if (j == k0 + 3) cb[nx][1][i] = nv;
            if ((i == k0 + 2 || i == k0 + 3) && (j == k0 + 2 || j == k0 + 3))
                spv[nx][(i - k0 - 2) * 2 + (j - k0 - 2)] = nv;
        }
        __syncthreads();
    }
}

// fused variant: at last stage adds S and primes buffers for the NEXT inversion
__device__ __forceinline__ void gj16b_fused(float (*M)[17], float (*rb)[2][DX],
                                            float (*cb)[2][DX], float (*spv)[4],
                                            int i, int j, float (*S)[17]) {
    #pragma unroll
    for (int s = 0; s < 8; ++s) {
        const int nx = (s & 1) ^ 1;
        const int k0 = 2 * s;
        float nv = gj_stage(M, rb, cb, spv, i, j, s);
        if (s < 7) {
            M[i][j] = nv;
            if (i == k0 + 2) rb[nx][0][j] = nv;
            if (i == k0 + 3) rb[nx][1][j] = nv;
            if (j == k0 + 2) cb[nx][0][i] = nv;
            if (j == k0 + 3) cb[nx][1][i] = nv;
            if ((i == k0 + 2 || i == k0 + 3) && (j == k0 + 2 || j == k0 + 3))
                spv[nx][(i - k0 - 2) * 2 + (j - k0 - 2)] = nv;
        } else {
            float nvs = nv + S[i][j];
            M[i][j] = nvs;
            if (i < 2) rb[0][i][j] = nvs;
            if (j < 2) cb[0][j][i] = nvs;
            if (i < 2 && j < 2) spv[0][i * 2 + j] = nvs;
        }
        __syncthreads();
    }
}

__global__ void k_init() { g_allones = 1; g_tc = 0; }

__global__ void k_scan(const float* __restrict__ gmask) {
    int idx = blockIdx.x * 256 + threadIdx.x;
    if (gmask[idx] != 1.0f) atomicAnd(&g_allones, 0);
}

// ---------------- K1: shared Riccati to steady state (1 CTA) ----------------
__global__ __launch_bounds__(256, 1)
void k1_riccati(const float* __restrict__ gA, const float* __restrict__ gC,
                const float* __restrict__ gLam0, const float* __restrict__ gWlog,
                const float* __restrict__ gRlog) {
    if (!g_allones) return;
    __shared__ float sA[DX][17], sCtRinvC[DX][17], sC[DA][17];
    __shared__ float sCtRinv[DX][33], sK[DX][33];
    __shared__ float sM[DX][17], sT[DX][17], sG[DX][17], sP[DX][17];
    __shared__ float rb[2][2][DX], cb[2][2][DX], spv[2][4];
    __shared__ float s_rinv[DA], sW[DX];

    const int tid = threadIdx.x;
    const int i = tid >> 4, j = tid & 15;

    sA[i][j] = gA[tid];
    for (int idx = tid; idx < DA * DX; idx += 256) sC[idx >> 4][idx & 15] = gC[idx];
    if (tid < DA) s_rinv[tid] = __expf(-gRlog[tid]);
    if (tid < DX) sW[tid] = __expf(gWlog[tid]);
    __syncthreads();
    for (int idx = tid; idx < DX * DA; idx += 256) {
        int x = idx >> 5, aa = idx & 31;
        sCtRinv[x][aa] = sC[aa][x] * s_rinv[aa];
    }
    __syncthreads();
    {
        float acc = 0.f;
        #pragma unroll
        for (int aa = 0; aa < DA; ++aa) acc = fmaf(sCtRinv[i][aa], sC[aa][j], acc);
        sCtRinvC[i][j] = acc;
    }
    {   // prime first inversion
        float v = gLam0[tid];
        sP[i][j] = v;
        sM[i][j] = v;
        if (i < 2) rb[0][i][j] = v;
        if (j < 2) cb[0][j][i] = v;
        if (i < 2 && j < 2) spv[0][i * 2 + j] = v;
    }
    __syncthreads();

    int tcv = -1;
    for (int t = 0; t < TC; ++t) {
        gj16b_fused(sM, rb, cb, spv, i, j, sCtRinvC);  // M = (P^-1 + S), primed
        gj16b(sM, rb, cb, spv, i, j);                  // M = Lam_t
        // phase A: K = Lam CtRinv, T = A Lam, store Lt
        {
            #pragma unroll
            for (int rep = 0; rep < 2; ++rep) {
                int idx = tid + rep * 256;
                int ri = idx >> 5, ca = idx & 31;
                float acc = 0.f;
                #pragma unroll
                for (int y = 0; y < DX; ++y) acc = fmaf(sM[ri][y], sCtRinv[y][ca], acc);
                sK[ri][ca] = acc;
            }
            float acc = 0.f;
            #pragma unroll
            for (int k = 0; k < DX; ++k) acc = fmaf(sA[i][k], sM[k][j], acc);
            sT[i][j] = acc;
            g_Lt[t][tid] = sM[i][j];
        }
        __syncthreads();
        // phase B: G = I - K C, store K
        {
            float kc = 0.f;
            #pragma unroll
            for (int aa = 0; aa < DA; ++aa) kc = fmaf(sK[i][aa], sC[aa][j], kc);
            sG[i][j] = ((i == j) ? 1.f : 0.f) - kc;
            #pragma unroll
            for (int rep = 0; rep < 2; ++rep) {
                int idx = tid + rep * 256;
                int ri = idx >> 5, ca = idx & 31;
                g_Kt[t][ri][ca] = sK[ri][ca];
            }
        }
        __syncthreads();
        // phase C: M_t = A G, N = A K, P' = T A^T + W; prime next inversion
        int pred;
        {
            float mm = 0.f;
            #pragma unroll
            for (int k = 0; k < DX; ++k) mm = fmaf(sA[i][k], sG[k][j], mm);
            g_Mt[t][i][j] = mm;
            g_Gt[t][i][j] = sG[i][j];
            #pragma unroll
            for (int rep = 0; rep < 2; ++rep) {
                int idx = tid + rep * 256;
                int ri = idx >> 5, ca = idx & 31;
                float acc = 0.f;
                #pragma unroll
                for (int y = 0; y < DX; ++y) acc = fmaf(sA[ri][y], sK[y][ca], acc);
                g_Nt[t][ri][ca] = acc;
            }
            float pn = (i == j) ? sW[i] : 0.f;
            #pragma unroll
            for (int k = 0; k < DX; ++k) pn = fmaf(sT[i][k], sA[j][k], pn);
            g_Lp[t][tid] = pn;
            pred = (fabsf(pn - sP[i][j]) > 1e-6f) ? 1 : 0;
            sP[i][j] = pn;
            sM[i][j] = pn;
            if (i < 2) rb[0][i][j] = pn;
            if (j < 2) cb[0][j][i] = pn;
            if (i < 2 && j < 2) spv[0][i * 2 + j] = pn;
        }
        int notconv = __syncthreads_or(pred);
        if (!notconv) { tcv = t; break; }
    }
    if (tid == 0) {
        if (tcv < 0) g_allones = 0;
        else g_tc = tcv;
    }
}

// ---------------- K2: d/f precompute + Lambda streaming (64 t/CTA) ----------
__global__ __launch_bounds__(256, 4)
void k2_dfl(const float* __restrict__ ga, const float* __restrict__ gu,
            const float* __restrict__ gB, float* __restrict__ out) {
    if (!g_allones) return;
    const int tc = g_tc;
    const int b = blockIdx.x >> 4;
    const int t0 = (blockIdx.x & 15) << 6;
    const int tid = threadIdx.x;
    const int w = tid >> 5, l = tid & 31;
    const int i = l & 15, h = l >> 4;

    __shared__ __align__(16) float s_a[64 * 32];
    __shared__ __align__(16) float s_u[64 * 16];
    __shared__ __align__(16) float sLp[256], sLt[256];

    {
        const float4* src = (const float4*)(ga + ((size_t)b * T_STEPS + t0) * DA);
        float4* dst = (float4*)s_a;
        dst[tid] = src[tid];
        dst[tid + 256] = src[tid + 256];
        const float4* srcu = (const float4*)(gu + ((size_t)b * T_STEPS + t0) * DX);
        ((float4*)s_u)[tid] = srcu[tid];
    }
    sLp[tid] = g_Lp[tc][tid];
    sLt[tid] = g_Lt[tc][tid];

    // steady N/K/B halves in registers
    float Np[16], Kp[16], Bp[8];
    #pragma unroll
    for (int c = 0; c < 16; ++c) {
        Np[c] = g_Nt[tc][i][16 * h + c];
        Kp[c] = g_Kt[tc][i][16 * h + c];
    }
    #pragma unroll
    for (int c = 0; c < 8; ++c) Bp[c] = gB[i * 16 + 8 * h + c];
    __syncthreads();

    // Lambda streaming first (fire-and-forget stores fill DRAM early)
    #pragma unroll
    for (int q = tid; q < 64 * 64; q += 256) {
        const int tt = t0 + (q >> 6), e4 = q & 63;
        float4 vp, vl;
        if (tt >= tc) {
            vp = ((const float4*)sLp)[e4];
            vl = ((const float4*)sLt)[e4];
        } else {
            vp = ((const float4*)g_Lp[tt])[e4];
            vl = ((const float4*)g_Lt[tt])[e4];
        }
        size_t off = ((size_t)tt * NB + b) * 256 + (size_t)e4 * 4;
        __stcs((float4*)(out + BASE_LP + off), vp);
        __stcs((float4*)(out + BASE_LT + off), vl);
    }

    // d/f compute: warp w handles t = t0 + w + 8*it
    #pragma unroll
    for (int it = 0; it < 8; ++it) {
        const int t = t0 + w + 8 * it;
        const int tl = t - t0;
        float d = 0.f, f = 0.f;
        if (t >= tc) {
            #pragma unroll
            for (int c = 0; c < 16; ++c) {
                float av = s_a[tl * 32 + 16 * h + c];
                d = fmaf(Np[c], av, d);
                f = fmaf(Kp[c], av, f);
            }
        } else {
            #pragma unroll
            for (int c = 0; c < 16; ++c) {
                float av = s_a[tl * 32 + 16 * h + c];
                d = fmaf(__ldg(&g_Nt[t][i][16 * h + c]), av, d);
                f = fmaf(__ldg(&g_Kt[t][i][16 * h + c]), av, f);
            }
        }
        if (t != T_STEPS - 1) {
            #pragma unroll
            for (int c = 0; c < 8; ++c)
                d = fmaf(Bp[c], s_u[tl * 16 + 8 * h + c], d);
        }
        d += __shfl_xor_sync(0xffffffffu, d, 16);
        f += __shfl_xor_sync(0xffffffffu, f, 16);
        if (h == 0) g_df[0][b][t][i] = d;
        else        g_df[1][b][t][i] = f;
    }
}

// ---------------- K3: chunked affine mu recursion ----------------
__global__ __launch_bounds__(256, 2)
void k3_mu(const float* __restrict__ gmu0, float* __restrict__ out) {
    if (!g_allones) return;
    const int tc = g_tc;
    const int b = blockIdx.x;
    const int warp = threadIdx.x >> 5, lane = threadIdx.x & 31, r = lane & 15;
    const int cs = warp * 128, ce = cs + 128;
    const int s = (warp == 0) ? 0 : cs - 64;

    float cst[16];
    {
        const float (*CF)[17] = (lane < 16) ? g_Mt[tc] : g_Gt[tc];
        #pragma unroll
        for (int k = 0; k < DX; ++k) cst[k] = CF[r][k];
    }
    const float* dfb = (lane < 16) ? &g_df[0][b][0][r] : &g_df[1][b][0][r];
    float mu = (warp == 0 && lane < 16) ? __ldg(&gmu0[r]) : 0.f;

    auto ld = [&](int t) { return __ldg(dfb + (size_t)t * DX); };
    auto body = [&](int t, const float* cf, float val) {
        float a0 = 0.f, a1 = 0.f, a2 = 0.f, a3 = 0.f;
        #pragma unroll
        for (int k = 0; k < DX; k += 4) {
            a0 = fmaf(cf[k],     __shfl_sync(0xffffffffu, mu, k),     a0);
            a1 = fmaf(cf[k + 1], __shfl_sync(0xffffffffu, mu, k + 1), a1);
            a2 = fmaf(cf[k + 2], __shfl_sync(0xffffffffu, mu, k + 2), a2);
            a3 = fmaf(cf[k + 3], __shfl_sync(0xffffffffu, mu, k + 3), a3);
        }
        float res = ((a0 + a1) + (a2 + a3)) + val;
        if (t >= cs)
            out[((lane < 16) ? BASE_MP : BASE_MT) + ((size_t)t * NB + b) * DX + r] = res;
        mu = res;
    };
    auto dostep = [&](int t, float val) {
        if (t < tc) {
            float cf[16];
            const float (*CF)[17] = (lane < 16) ? g_Mt[t] : g_Gt[t];
            #pragma unroll
            for (int k = 0; k < DX; ++k) cf[k] = __ldg(&CF[r][k]);
            body(t, cf, val);
        } else {
            body(t, cst, val);
        }
    };

    int t = s;
    float v0 = ld(t), v1 = ld(t + 1), v2 = ld(t + 2), v3 = ld(t + 3);
    for (; t < ce; t += 4) {
        dostep(t, v0);     v0 = (t + 4 < ce) ? ld(t + 4) : 0.f;
        dostep(t + 1, v1); v1 = (t + 5 < ce) ? ld(t + 5) : 0.f;
        dostep(t + 2, v2); v2 = (t + 6 < ce) ? ld(t + 6) : 0.f;
        dostep(t + 3, v3); v3 = (t + 7 < ce) ? ld(t + 7) : 0.f;
    }
}

// ---------------- Fallback: full general-mask kernel (guarded) ----------
__global__ __launch_bounds__(256, 2)
void ldm_fallback(const float* __restrict__ ga, const float* __restrict__ gu,
                  const float* __restrict__ gmask, const float* __restrict__ gA,
                  const float* __restrict__ gB, const float* __restrict__ gC,
                  const float* __restrict__ gmu0, const float* __restrict__ gLam0,
                  const float* __restrict__ gWlog, const float* __restrict__ gRlog,
                  float* __restrict__ out) {
    if (g_allones) return;
    __shared__ float sA[DX][17], sB[DX][17], sCtRinvC[DX][17];
    __shared__ float sC[DA][17];
    __shared__ float sCtRinv[DX][33], sK[DX][33];
    __shared__ float sM[DX][17], sT[DX][17], sLt[DX][17], sKC[DX][17];
    __shared__ float sP[2][DX][17];
    __shared__ float rb[2][2][DX], cb[2][2][DX], spv[2][4];
    __shared__ float s_rinv[DA], sW[DX];
    __shared__ float s_mu[DX], s_mut[DX], s_r[DA], s_u[DX];
    __shared__ __align__(16) float sPflat[256];
    __shared__ __align__(16) float sLtflat[256];
    __shared__ float s_mask[T_STEPS];
    __shared__ int sFlag;
    __shared__ int sLastMasked;

    const int tid = threadIdx.x;
    const int i = tid >> 4, j = tid & 15;
    const int b = blockIdx.x;

    if (tid == 0) sLastMasked = -1;
    __syncthreads();
    sA[i][j] = gA[tid];
    sB[i][j] = gB[tid];
    for (int idx = tid; idx < DA * DX; idx += 256) sC[idx >> 4][idx & 15] = gC[idx];
    if (tid < DA) s_rinv[tid] = __expf(-gRlog[tid]);
    if (tid < DX) { sW[tid] = __expf(gWlog[tid]); s_mu[tid] = gmu0[tid]; }
    sP[0][i][j] = gLam0[tid];
    #pragma unroll
    for (int rep = 0; rep < T_STEPS / 256; ++rep) {
        int idx = tid + rep * 256;
        float mv = gmask[(size_t)b * T_STEPS + idx];
        s_mask[idx] = mv;
        if (mv != 1.0f) atomicMax(&sLastMasked, idx);
    }
    __syncthreads();
    for (int idx = tid; idx < DX * DA; idx += 256) {
        int x = idx >> 5, aa = idx & 31;
        sCtRinv[x][aa] = sC[aa][x] * s_rinv[aa];
    }
    __syncthreads();
    {
        float acc = 0.f;
        #pragma unroll
        for (int aa = 0; aa < DA; ++aa) acc = fmaf(sCtRinv[i][aa], sC[aa][j], acc);
        sCtRinvC[i][j] = acc;
    }
    __syncthreads();

    int cur = 0;
    int t_frozen = T_STEPS;
    const int lastMasked = sLastMasked;

    for (int t = 0; t < T_STEPS; ++t) {
        if (tid == 0) sFlag = 0;
        const float m = s_mask[t];
        const bool m1 = (m == 1.0f);
        float rga = 0.f, rgu = 0.f;
        if (tid < DA) {
            rga = __ldg(&ga[((size_t)b * T_STEPS + t) * DA + tid]);
        } else if (tid < DA + DX) {
            rgu = (t == T_STEPS - 1) ? 0.f
                : __ldg(&gu[((size_t)b * T_STEPS + t) * DX + (tid - DA)]);
        }
        {
            float v = sP[cur][i][j];
            sM[i][j] = v;
            if (i < 2) rb[0][i][j] = v;
            if (j < 2) cb[0][j][i] = v;
            if (i < 2 && j < 2) spv[0][i * 2 + j] = v;
        }
        __syncthreads();
        gj16b(sM, rb, cb, spv, i, j);
        {
            float nv = sM[i][j] + sCtRinvC[i][j];
            sM[i][j] = nv;
            if (i < 2) rb[0][i][j] = nv;
            if (j < 2) cb[0][j][i] = nv;
            if (i < 2 && j < 2) spv[0][i * 2 + j] = nv;
        }
        __syncthreads();
        gj16b(sM, rb, cb, spv, i, j);
        {
            #pragma unroll
            for (int rep = 0; rep < 2; ++rep) {
                int idx = tid + rep * 256;
                int ri = idx >> 5, ca = idx & 31;
                float acc = 0.f;
                #pragma unroll
                for (int y = 0; y < DX; ++y) acc = fmaf(sM[ri][y], sCtRinv[y][ca], acc);
                sK[ri][ca] = acc;
            }
            float acc = 0.f;
            #pragma unroll
            for (int k = 0; k < DX; ++k) acc = fmaf(sA[i][k], sM[k][j], acc);
            sT[i][j] = acc;
            if (m1) sLt[i][j] = sM[i][j];
        }
        __syncthreads();
        if (!m1) {
            float acc = 0.f;
            #pragma unroll
            for (int aa = 0; aa < DA; ++aa) acc = fmaf(sK[i][aa], sC[aa][j], acc);
            sKC[i][j] = acc;
            __syncthreads();
            float acc2 = 0.f;
            #pragma unroll
            for (int k = 0; k < DX; ++k) acc2 = fmaf(sKC[i][k], sP[cur][k][j], acc2);
            sLt[i][j] = sP[cur][i][j] - m * acc2;
            __syncthreads();
            float acc3 = 0.f;
            #pragma unroll
            for (int k = 0; k < DX; ++k) acc3 = fmaf(sA[i][k], sLt[k][j], acc3);
            sT[i][j] = acc3;
            __syncthreads();
        }
        const int nxt = cur ^ 1;
        {
            float acc = (i == j) ? sW[i] : 0.f;
            #pragma unroll
            for (int k = 0; k < DX; ++k) acc = fmaf(sT[i][k], sA[j][k], acc);
            sP[nxt][i][j] = acc;
            if (fabsf(acc - sP[cur][i][j]) > 1e-6f) sFlag = 1;
            size_t off = ((size_t)t * NB + b) * 256 + tid;
            out[BASE_LP + off] = acc;
            out[BASE_LT + off] = sLt[i][j];
            if (tid < DA) {
                float ap = 0.f;
                #pragma unroll
                for (int k = 0; k < DX; ++k) ap = fmaf(sC[tid][k], s_mu[k], ap);
                s_r[tid] = fmaf(m, rga, -ap);
            } else if (tid < DA + DX) {
                s_u[tid - DA] = rgu;
            }
        }
        __syncthreads();
        if (tid < DX) {
            float acc = 0.f;
            #pragma unroll
            for (int aa = 0; aa < DA; ++aa) acc = fmaf(sK[tid][aa], s_r[aa], acc);
            float mt = s_mu[tid] + m * acc;
            s_mut[tid] = mt;
            out[BASE_MT + ((size_t)t * NB + b) * DX + tid] = mt;
        }
        __syncthreads();
        if (tid < DX) {
            float acc = 0.f;
            #pragma unroll
            for (int k = 0; k < DX; ++k) acc = fmaf(sA[tid][k], s_mut[k], acc);
            #pragma unroll
            for (int k = 0; k < DX; ++k) acc = fmaf(sB[tid][k], s_u[k], acc);
            s_mu[tid] = acc;
            out[BASE_MP + ((size_t)t * NB + b) * DX + tid] = acc;
        }
        const bool conv = m1 && (sFlag == 0) && (t >= lastMasked);
        __syncthreads();
        cur = nxt;
        if (conv) { t_frozen = t; break; }
    }

    if (t_frozen < T_STEPS) {
        sPflat[tid]  = sP[cur][i][j];
        sLtflat[tid] = sLt[i][j];
        __syncthreads();
        const int warp = tid >> 5, lane = tid & 31, lr = lane & 15;
        const int t0f = t_frozen + 1;
        const int n = T_STEPS - t0f;
        const int L = (n + 7) / 8;
        const int cs = t0f + warp * L;
        const int ce = min(cs + L, T_STEPS);
        const int tb = (warp == 0) ? t0f : cs - L;
        const float4* pf = (const float4*)sPflat;
        const float4* lf = (const float4*)sLtflat;
        const float4 p0 = pf[2 * lane], p1 = pf[2 * lane + 1];
        const float4 l0 = lf[2 * lane], l1 = lf[2 * lane + 1];
        int tt = t0f + warp;
        float Crow[DX], Krow[DA];
        #pragma unroll
        for (int k = 0; k < DX; ++k) Crow[k] = sC[lane][k];
        #pragma unroll
        for (int aa = 0; aa < DA; ++aa) Krow[aa] = sK[lr][aa];
        float mu = (warp == 0) ? s_mu[lr] : 0.f;
        for (int t = tb; t < ce; ++t) {
            const float m = s_mask[t];
            const float av = __ldg(&ga[((size_t)b * T_STEPS + t) * DA + lane]);
            const float uv = (lane < DX && t < T_STEPS - 1)
                ? __ldg(&gu[((size_t)b * T_STEPS + t) * DX + lane]) : 0.f;
            if (tt < T_STEPS) {
                size_t off = ((size_t)tt * NB + b) * 256 + lane * 8;
                float4* o1 = (float4*)(out + BASE_LP + off);
                o1[0] = p0; o1[1] = p1;
                float4* o2 = (float4*)(out + BASE_LT + off);
                o2[0] = l0; o2[1] = l1;
                tt += 8;
            }
            float ap0 = 0.f, ap1 = 0.f;
            #pragma unroll
            for (int k = 0; k < DX; k += 2) {
                ap0 = fmaf(Crow[k],     __shfl_sync(0xffffffffu, mu, k),     ap0);
                ap1 = fmaf(Crow[k + 1], __shfl_sync(0xffffffffu, mu, k + 1), ap1);
            }
            const float r = fmaf(m, av, -(ap0 + ap1));
            float g0 = 0.f, g1 = 0.f, g2 = 0.f, g3 = 0.f;
            #pragma unroll
            for (int aa = 0; aa < DA; aa += 4) {
                g0 = fmaf(Krow[aa],     __shfl_sync(0xffffffffu, r, aa),     g0);
                g1 = fmaf(Krow[aa + 1], __shfl_sync(0xffffffffu, r, aa + 1), g1);
                g2 = fmaf(Krow[aa + 2], __shfl_sync(0xffffffffu, r, aa + 2), g2);
                g3 = fmaf(Krow[aa + 3], __shfl_sync(0xffffffffu, r, aa + 3), g3);
            }
            const float mt = fmaf(m, (g0 + g1) + (g2 + g3), mu);
            float mun = 0.f;
            #pragma unroll
            for (int k = 0; k < DX; ++k) {
                mun = fmaf(sA[lr][k], __shfl_sync(0xffffffffu, mt, k), mun);
                mun = fmaf(sB[lr][k], __shfl_sync(0xffffffffu, uv, k), mun);
            }
            if (t >= cs && lane < DX) {
                out[BASE_MT + ((size_t)t * NB + b) * DX + lane] = mt;
                out[BASE_MP + ((size_t)t * NB + b) * DX + lane] = mun;
            }
            mu = mun;
        }
        for (; tt < T_STEPS; tt += 8) {
            size_t off = ((size_t)tt * NB + b) * 256 + lane * 8;
            float4* o1 = (float4*)(out + BASE_LP + off);
            o1[0] = p0; o1[1] = p1;
            float4* o2 = (float4*)(out + BASE_LT + off);
            o2[0] = l0; o2[1] = l1;
        }
    }
}

extern "C" void kernel_launch(void* const* d_in, const int* in_sizes, int n_in,
                              void* d_out, int out_size) {
    (void)in_sizes; (void)n_in; (void)out_size;
    const float* ga    = (const float*)d_in[0];
    const float* gu    = (const float*)d_in[1];
    const float* gmask = (const float*)d_in[2];
    const float* gA    = (const float*)d_in[3];
    const float* gB    = (const float*)d_in[4];
    const float* gC    = (const float*)d_in[5];
    const float* gmu0  = (const float*)d_in[6];
    const float* gLam0 = (const float*)d_in[7];
    const float* gWlog = (const float*)d_in[8];
    const float* gRlog = (const float*)d_in[9];
    float* out = (float*)d_out;

    k_init<<<1, 1>>>();
    k_scan<<<(NB * T_STEPS) / 256, 256>>>(gmask);
    k1_riccati<<<1, 256>>>(gA, gC, gLam0, gWlog, gRlog);
    k2_dfl<<<NB * 16, 256>>>(ga, gu, gB, out);
    k3_mu<<<NB, 256>>>(gmu0, out);
    ldm_fallback<<<NB, 256>>>(ga, gu, gmask, gA, gB, gC, gmu0, gLam0,
                              gWlog, gRlog, out);
}

// round 9
// speedup vs baseline: 5.1439x; 1.1230x over previous
#include <cuda_runtime.h>

// LDM Kalman forward, 256 seq x 1024 steps, 5 launches:
//   k_scan     : per-CTA mask==1 flags into g_bad (no init kernel needed)
//   k1_riccati : reduces g_bad; shared Riccati to steady state (1 CTA) using
//                single-inversion form Lam_t = (I + P S)^-1 P  (13 syncs/step)
//   k2_dfl     : 64 t/CTA; d=N a+B u, f=K a; streams all Lambda outputs
//   k3_mu      : chunked affine mu recursion (burn-in), 16 shfl+16 FMA/step
//   fallback   : full general-mask kernel (guarded)

#define T_STEPS 1024
#define NB 256
#define DX 16
#define DA 32
#define TC 192

#define BASE_MP 0ul
#define BASE_MT 4194304ul
#define BASE_LP 8388608ul
#define BASE_LT 75497472ul

__device__ int g_allones;
__device__ int g_tc;
__device__ int g_bad[1024];
__device__ float g_Mt[TC][DX][17];
__device__ float g_Gt[TC][DX][17];
__device__ float g_Nt[TC][DX][33];
__device__ float g_Kt[TC][DX][33];
__device__ __align__(16) float g_Lp[TC][256];
__device__ __align__(16) float g_Lt[TC][256];
__device__ float g_df[2][NB][T_STEPS][DX];

__device__ __forceinline__ float frcp_acc(float x) {
    float r;
    asm("rcp.approx.f32 %0, %1;" : "=f"(r) : "f"(x));
    float e = __fmaf_rn(-x, r, 1.0f);
    r = __fmaf_rn(r, e, r);
    return r;
}

__device__ __forceinline__ float gj_stage(float (*M)[17], float (*rb)[2][DX],
                                          float (*cb)[2][DX], float (*spv)[4],
                                          int i, int j, int s) {
    const int par = s & 1;
    const int k0 = 2 * s, k1 = 2 * s + 1;
    const float p00 = spv[par][0], p01 = spv[par][1];
    const float p10 = spv[par][2], p11 = spv[par][3];
    const float rd = frcp_acc(__fmaf_rn(p00, p11, -(p01 * p10)));
    const float q00 = p11 * rd, q01 = -p01 * rd;
    const float q10 = -p10 * rd, q11 = p00 * rd;
    const float r0 = rb[par][0][j], r1 = rb[par][1][j];
    const float c0 = cb[par][0][i], c1 = cb[par][1][i];
    const float v = M[i][j];
    const float w0 = __fmaf_rn(q00, r0, q01 * r1);
    const float w1 = __fmaf_rn(q10, r0, q11 * r1);
    const bool ip = (i == k0) || (i == k1);
    const bool jp = (j == k0) || (j == k1);
    float nv;
    if (ip && jp)      nv = (i == k0) ? ((j == k0) ? q00 : q01)
                                      : ((j == k0) ? q10 : q11);
    else if (ip)       nv = (i == k0) ? w0 : w1;
    else if (jp)       nv = (j == k0) ? -__fmaf_rn(c0, q00, c1 * q10)
                                      : -__fmaf_rn(c0, q01, c1 * q11);
    else               nv = v - __fmaf_rn(c0, w0, c1 * w1);
    return nv;
}

__device__ __forceinline__ void gj16b(float (*M)[17], float (*rb)[2][DX],
                                      float (*cb)[2][DX], float (*spv)[4],
                                      int i, int j) {
    #pragma unroll
    for (int s = 0; s < 8; ++s) {
        const int nx = (s & 1) ^ 1;
        const int k0 = 2 * s;
        float nv = gj_stage(M, rb, cb, spv, i, j, s);
        M[i][j] = nv;
        if (s < 7) {
            if (i == k0 + 2) rb[nx][0][j] = nv;
            if (i == k0 + 3) rb[nx][1][j] = nv;
            if (j == k0 + 2) cb[nx][0][i] = nv;
            if (j == k0 + 3) cb[nx][1][i] = nv;
            if ((i == k0 + 2 || i == k0 + 3) && (j == k0 + 2 || j == k0 + 3))
                spv[nx][(i - k0 - 2) * 2 + (j - k0 - 2)] = nv;
        }
        __syncthreads();
    }
}

__global__ void k_scan(const float* __restrict__ gmask) {
    int idx = blockIdx.x * 256 + threadIdx.x;
    int bad = (gmask[idx] != 1.0f) ? 1 : 0;
    int any = __syncthreads_or(bad);
    if (threadIdx.x == 0) g_bad[blockIdx.x] = any;  // unconditional: no init
}

// ---------------- K1: shared Riccati (single inversion per step) ------------
__global__ __launch_bounds__(256, 1)
void k1_riccati(const float* __restrict__ gA, const float* __restrict__ gC,
                const float* __restrict__ gLam0, const float* __restrict__ gWlog,
                const float* __restrict__ gRlog) {
    __shared__ float sA[DX][17], sS[DX][17], sC[DA][17];
    __shared__ float sCtRinv[DX][33], sK[DX][33];
    __shared__ float sM[DX][17], sT[DX][17], sG[DX][17], sP[DX][17], sLam[DX][17];
    __shared__ float rb[2][2][DX], cb[2][2][DX], spv[2][4];
    __shared__ float s_rinv[DA], sW[DX];

    const int tid = threadIdx.x;
    const int i = tid >> 4, j = tid & 15;

    // mask all-ones reduction from g_bad
    {
        int bad = 0;
        #pragma unroll
        for (int r = 0; r < 4; ++r) bad |= g_bad[tid + r * 256];
        int any = __syncthreads_or(bad);
        if (any) { if (tid == 0) { g_allones = 0; g_tc = 0; } return; }
    }

    sA[i][j] = gA[tid];
    for (int idx = tid; idx < DA * DX; idx += 256) sC[idx >> 4][idx & 15] = gC[idx];
    if (tid < DA) s_rinv[tid] = __expf(-gRlog[tid]);
    if (tid < DX) sW[tid] = __expf(gWlog[tid]);
    sP[i][j] = gLam0[tid];
    __syncthreads();
    for (int idx = tid; idx < DX * DA; idx += 256) {
        int x = idx >> 5, aa = idx & 31;
        sCtRinv[x][aa] = sC[aa][x] * s_rinv[aa];
    }
    __syncthreads();
    {
        float acc = 0.f;
        #pragma unroll
        for (int aa = 0; aa < DA; ++aa) acc = fmaf(sCtRinv[i][aa], sC[aa][j], acc);
        sS[i][j] = acc;   // S = C^T R^-1 C
    }
    __syncthreads();

    int tcv = -1;
    for (int t = 0; t < TC; ++t) {
        // p0: X = I + P S, prime GJ buffers
        {
            float x = (i == j) ? 1.f : 0.f;
            #pragma unroll
            for (int k = 0; k < DX; ++k) x = fmaf(sP[i][k], sS[k][j], x);
            sM[i][j] = x;
            if (i < 2) rb[0][i][j] = x;
            if (j < 2) cb[0][j][i] = x;
            if (i < 2 && j < 2) spv[0][i * 2 + j] = x;
        }
        __syncthreads();
        gj16b(sM, rb, cb, spv, i, j);             // sM = X^-1   [8 syncs]
        // p1: Lam = X^-1 P
        {
            float acc = 0.f;
            #pragma unroll
            for (int k = 0; k < DX; ++k) acc = fmaf(sM[i][k], sP[k][j], acc);
            sLam[i][j] = acc;
            g_Lt[t][tid] = acc;
        }
        __syncthreads();
        // p2: K = Lam CtRinv ; T = A Lam
        {
            #pragma unroll
            for (int rep = 0; rep < 2; ++rep) {
                int idx = tid + rep * 256;
                int ri = idx >> 5, ca = idx & 31;
                float acc = 0.f;
                #pragma unroll
                for (int y = 0; y < DX; ++y) acc = fmaf(sLam[ri][y], sCtRinv[y][ca], acc);
                sK[ri][ca] = acc;
            }
            float acc = 0.f;
            #pragma unroll
            for (int k = 0; k < DX; ++k) acc = fmaf(sA[i][k], sLam[k][j], acc);
            sT[i][j] = acc;
        }
        __syncthreads();
        // p3: G = I - K C ; store K
        {
            float kc = 0.f;
            #pragma unroll
            for (int aa = 0; aa < DA; ++aa) kc = fmaf(sK[i][aa], sC[aa][j], kc);
            sG[i][j] = ((i == j) ? 1.f : 0.f) - kc;
            #pragma unroll
            for (int rep = 0; rep < 2; ++rep) {
                int idx = tid + rep * 256;
                int ri = idx >> 5, ca = idx & 31;
                g_Kt[t][ri][ca] = sK[ri][ca];
            }
        }
        __syncthreads();
        // p4: M = A G, N = A K, P' = T A^T + W, convergence
        int pred;
        {
            float mm = 0.f;
            #pragma unroll
            for (int k = 0; k < DX; ++k) mm = fmaf(sA[i][k], sG[k][j], mm);
            g_Mt[t][i][j] = mm;
            g_Gt[t][i][j] = sG[i][j];
            #pragma unroll
            for (int rep = 0; rep < 2; ++rep) {
                int idx = tid + rep * 256;
                int ri = idx >> 5, ca = idx & 31;
                float acc = 0.f;
                #pragma unroll
                for (int y = 0; y < DX; ++y) acc = fmaf(sA[ri][y], sK[y][ca], acc);
                g_Nt[t][ri][ca] = acc;
            }
            float pn = (i == j) ? sW[i] : 0.f;
            #pragma unroll
            for (int k = 0; k < DX; ++k) pn = fmaf(sT[i][k], sA[j][k], pn);
            g_Lp[t][tid] = pn;
            pred = (fabsf(pn - sP[i][j]) > 1e-6f) ? 1 : 0;
            sP[i][j] = pn;
        }
        int notconv = __syncthreads_or(pred);
        if (!notconv) { tcv = t; break; }
    }
    if (tid == 0) {
        if (tcv < 0) { g_allones = 0; g_tc = 0; }
        else { g_allones = 1; g_tc = tcv; }
    }
}

// ---------------- K2: d/f precompute + Lambda streaming (64 t/CTA) ----------
__global__ __launch_bounds__(256, 4)
void k2_dfl(const float* __restrict__ ga, const float* __restrict__ gu,
            const float* __restrict__ gB, float* __restrict__ out) {
    if (!g_allones) return;
    const int tc = g_tc;
    const int b = blockIdx.x >> 4;
    const int t0 = (blockIdx.x & 15) << 6;
    const int tid = threadIdx.x;
    const int w = tid >> 5, l = tid & 31;
    const int i = l & 15, h = l >> 4;

    __shared__ __align__(16) float s_a[64 * 32];
    __shared__ __align__(16) float s_u[64 * 16];
    __shared__ __align__(16) float sLp[256], sLt[256];

    {
        const float4* src = (const float4*)(ga + ((size_t)b * T_STEPS + t0) * DA);
        float4* dst = (float4*)s_a;
        dst[tid] = src[tid];
        dst[tid + 256] = src[tid + 256];
        const float4* srcu = (const float4*)(gu + ((size_t)b * T_STEPS + t0) * DX);
        ((float4*)s_u)[tid] = srcu[tid];
    }
    sLp[tid] = g_Lp[tc][tid];
    sLt[tid] = g_Lt[tc][tid];

    float Np[16], Kp[16], Bp[8];
    #pragma unroll
    for (int c = 0; c < 16; ++c) {
        Np[c] = g_Nt[tc][i][16 * h + c];
        Kp[c] = g_Kt[tc][i][16 * h + c];
    }
    #pragma unroll
    for (int c = 0; c < 8; ++c) Bp[c] = gB[i * 16 + 8 * h + c];
    __syncthreads();

    // steady-state Lambda values: loop-invariant per thread (e4 = tid & 63)
    const int e4c = tid & 63;
    const float4 vps = ((const float4*)sLp)[e4c];
    const float4 vls = ((const float4*)sLt)[e4c];
    #pragma unroll
    for (int it = 0; it < 16; ++it) {
        const int q = tid + it * 256;
        const int tt = t0 + (q >> 6);
        float4 vp, vl;
        if (tt >= tc) { vp = vps; vl = vls; }
        else {
            vp = ((const float4*)g_Lp[tt])[e4c];
            vl = ((const float4*)g_Lt[tt])[e4c];
        }
        size_t off = ((size_t)tt * NB + b) * 256 + (size_t)e4c * 4;
        __stcs((float4*)(out + BASE_LP + off), vp);
        __stcs((float4*)(out + BASE_LT + off), vl);
    }

    #pragma unroll
    for (int it = 0; it < 8; ++it) {
        const int t = t0 + w + 8 * it;
        const int tl = t - t0;
        float d = 0.f, f = 0.f;
        if (t >= tc) {
            #pragma unroll
            for (int c = 0; c < 16; ++c) {
                float av = s_a[tl * 32 + 16 * h + c];
                d = fmaf(Np[c], av, d);
                f = fmaf(Kp[c], av, f);
            }
        } else {
            #pragma unroll
            for (int c = 0; c < 16; ++c) {
                float av = s_a[tl * 32 + 16 * h + c];
                d = fmaf(__ldg(&g_Nt[t][i][16 * h + c]), av, d);
                f = fmaf(__ldg(&g_Kt[t][i][16 * h + c]), av, f);
            }
        }
        if (t != T_STEPS - 1) {
            #pragma unroll
            for (int c = 0; c < 8; ++c)
                d = fmaf(Bp[c], s_u[tl * 16 + 8 * h + c], d);
        }
        d += __shfl_xor_sync(0xffffffffu, d, 16);
        f += __shfl_xor_sync(0xffffffffu, f, 16);
        if (h == 0) g_df[0][b][t][i] = d;
        else        g_df[1][b][t][i] = f;
    }
}

// ---------------- K3: chunked affine mu recursion ----------------
__global__ __launch_bounds__(256, 2)
void k3_mu(const float* __restrict__ gmu0, float* __restrict__ out) {
    if (!g_allones) return;
    const int tc = g_tc;
    const int b = blockIdx.x;
    const int warp = threadIdx.x >> 5, lane = threadIdx.x & 31, r = lane & 15;
    const int cs = warp * 128, ce = cs + 128;
    const int s = (warp == 0) ? 0 : cs - 64;

    float cst[16];
    {
        const float (*CF)[17] = (lane < 16) ? g_Mt[tc] : g_Gt[tc];
        #pragma unroll
        for (int k = 0; k < DX; ++k) cst[k] = CF[r][k];
    }
    const float* dfb = (lane < 16) ? &g_df[0][b][0][r] : &g_df[1][b][0][r];
    float mu = (warp == 0 && lane < 16) ? __ldg(&gmu0[r]) : 0.f;

    auto ld = [&](int t) { return __ldg(dfb + (size_t)t * DX); };
    auto body = [&](int t, const float* cf, float val) {
        float a0 = 0.f, a1 = 0.f, a2 = 0.f, a3 = 0.f;
        #pragma unroll
        for (int k = 0; k < DX; k += 4) {
            a0 = fmaf(cf[k],     __shfl_sync(0xffffffffu, mu, k),     a0);
            a1 = fmaf(cf[k + 1], __shfl_sync(0xffffffffu, mu, k + 1), a1);
            a2 = fmaf(cf[k + 2], __shfl_sync(0xffffffffu, mu, k + 2), a2);
            a3 = fmaf(cf[k + 3], __shfl_sync(0xffffffffu, mu, k + 3), a3);
        }
        float res = ((a0 + a1) + (a2 + a3)) + val;
        if (t >= cs)
            out[((lane < 16) ? BASE_MP : BASE_MT) + ((size_t)t * NB + b) * DX + r] = res;
        mu = res;
    };
    auto dostep = [&](int t, float val) {
        if (t < tc) {
            float cf[16];
            const float (*CF)[17] = (lane < 16) ? g_Mt[t] : g_Gt[t];
            #pragma unroll
            for (int k = 0; k < DX; ++k) cf[k] = __ldg(&CF[r][k]);
            body(t, cf, val);
        } else {
            body(t, cst, val);
        }
    };

    int t = s;
    float v0 = ld(t), v1 = ld(t + 1), v2 = ld(t + 2), v3 = ld(t + 3);
    for (; t < ce; t += 4) {
        dostep(t, v0);     v0 = (t + 4 < ce) ? ld(t + 4) : 0.f;
        dostep(t + 1, v1); v1 = (t + 5 < ce) ? ld(t + 5) : 0.f;
        dostep(t + 2, v2); v2 = (t + 6 < ce) ? ld(t + 6) : 0.f;
        dostep(t + 3, v3); v3 = (t + 7 < ce) ? ld(t + 7) : 0.f;
    }
}

// ---------------- Fallback: full general-mask kernel (guarded) ----------
__global__ __launch_bounds__(256, 2)
void ldm_fallback(const float* __restrict__ ga, const float* __restrict__ gu,
                  const float* __restrict__ gmask, const float* __restrict__ gA,
                  const float* __restrict__ gB, const float* __restrict__ gC,
                  const float* __restrict__ gmu0, const float* __restrict__ gLam0,
                  const float* __restrict__ gWlog, const float* __restrict__ gRlog,
                  float* __restrict__ out) {
    if (g_allones) return;
    __shared__ float sA[DX][17], sB[DX][17], sCtRinvC[DX][17];
    __shared__ float sC[DA][17];
    __shared__ float sCtRinv[DX][33], sK[DX][33];
    __shared__ float sM[DX][17], sT[DX][17], sLt[DX][17], sKC[DX][17];
    __shared__ float sP[2][DX][17];
    __shared__ float rb[2][2][DX], cb[2][2][DX], spv[2][4];
    __shared__ float s_rinv[DA], sW[DX];
    __shared__ float s_mu[DX], s_mut[DX], s_r[DA], s_u[DX];
    __shared__ __align__(16) float sPflat[256];
    __shared__ __align__(16) float sLtflat[256];
    __shared__ float s_mask[T_STEPS];
    __shared__ int sFlag;
    __shared__ int sLastMasked;

    const int tid = threadIdx.x;
    const int i = tid >> 4, j = tid & 15;
    const int b = blockIdx.x;

    if (tid == 0) sLastMasked = -1;
    __syncthreads();
    sA[i][j] = gA[tid];
    sB[i][j] = gB[tid];
    for (int idx = tid; idx < DA * DX; idx += 256) sC[idx >> 4][idx & 15] = gC[idx];
    if (tid < DA) s_rinv[tid] = __expf(-gRlog[tid]);
    if (tid < DX) { sW[tid] = __expf(gWlog[tid]); s_mu[tid] = gmu0[tid]; }
    sP[0][i][j] = gLam0[tid];
    #pragma unroll
    for (int rep = 0; rep < T_STEPS / 256; ++rep) {
        int idx = tid + rep * 256;
        float mv = gmask[(size_t)b * T_STEPS + idx];
        s_mask[idx] = mv;
        if (mv != 1.0f) atomicMax(&sLastMasked, idx);
    }
    __syncthreads();
    for (int idx = tid; idx < DX * DA; idx += 256) {
        int x = idx >> 5, aa = idx & 31;
        sCtRinv[x][aa] = sC[aa][x] * s_rinv[aa];
    }
    __syncthreads();
    {
        float acc = 0.f;
        #pragma unroll
        for (int aa = 0; aa < DA; ++aa) acc = fmaf(sCtRinv[i][aa], sC[aa][j], acc);
        sCtRinvC[i][j] = acc;
    }
    __syncthreads();

    int cur = 0;
    int t_frozen = T_STEPS;
    const int lastMasked = sLastMasked;

    for (int t = 0; t < T_STEPS; ++t) {
        if (tid == 0) sFlag = 0;
        const float m = s_mask[t];
        const bool m1 = (m == 1.0f);
        float rga = 0.f, rgu = 0.f;
        if (tid < DA) {
            rga = __ldg(&ga[((size_t)b * T_STEPS + t) * DA + tid]);
        } else if (tid < DA + DX) {
            rgu = (t == T_STEPS - 1) ? 0.f
                : __ldg(&gu[((size_t)b * T_STEPS + t) * DX + (tid - DA)]);
        }
        {
            float v = sP[cur][i][j];
            sM[i][j] = v;
            if (i < 2) rb[0][i][j] = v;
            if (j < 2) cb[0][j][i] = v;
            if (i < 2 && j < 2) spv[0][i * 2 + j] = v;
        }
        __syncthreads();
        gj16b(sM, rb, cb, spv, i, j);
        {
            float nv = sM[i][j] + sCtRinvC[i][j];
            sM[i][j] = nv;
            if (i < 2) rb[0][i][j] = nv;
            if (j < 2) cb[0][j][i] = nv;
            if (i < 2 && j < 2) spv[0][i * 2 + j] = nv;
        }
        __syncthreads();
        gj16b(sM, rb, cb, spv, i, j);
        {
            #pragma unroll
            for (int rep = 0; rep < 2; ++rep) {
                int idx = tid + rep * 256;
                int ri = idx >> 5, ca = idx & 31;
                float acc = 0.f;
                #pragma unroll
                for (int y = 0; y < DX; ++y) acc = fmaf(sM[ri][y], sCtRinv[y][ca], acc);
                sK[ri][ca] = acc;
            }
            float acc = 0.f;
            #pragma unroll
            for (int k = 0; k < DX; ++k) acc = fmaf(sA[i][k], sM[k][j], acc);
            sT[i][j] = acc;
            if (m1) sLt[i][j] = sM[i][j];
        }
        __syncthreads();
        if (!m1) {
            float acc = 0.f;
            #pragma unroll
            for (int aa = 0; aa < DA; ++aa) acc = fmaf(sK[i][aa], sC[aa][j], acc);
            sKC[i][j] = acc;
            __syncthreads();
            float acc2 = 0.f;
            #pragma unroll
            for (int k = 0; k < DX; ++k) acc2 = fmaf(sKC[i][k], sP[cur][k][j], acc2);
            sLt[i][j] = sP[cur][i][j] - m * acc2;
            __syncthreads();
            float acc3 = 0.f;
            #pragma unroll
            for (int k = 0; k < DX; ++k) acc3 = fmaf(sA[i][k], sLt[k][j], acc3);
            sT[i][j] = acc3;
            __syncthreads();
        }
        const int nxt = cur ^ 1;
        {
            float acc = (i == j) ? sW[i] : 0.f;
            #pragma unroll
            for (int k = 0; k < DX; ++k) acc = fmaf(sT[i][k], sA[j][k], acc);
            sP[nxt][i][j] = acc;
            if (fabsf(acc - sP[cur][i][j]) > 1e-6f) sFlag = 1;
            size_t off = ((size_t)t * NB + b) * 256 + tid;
            out[BASE_LP + off] = acc;
            out[BASE_LT + off] = sLt[i][j];
            if (tid < DA) {
                float ap = 0.f;
                #pragma unroll
                for (int k = 0; k < DX; ++k) ap = fmaf(sC[tid][k], s_mu[k], ap);
                s_r[tid] = fmaf(m, rga, -ap);
            } else if (tid < DA + DX) {
                s_u[tid - DA] = rgu;
            }
        }
        __syncthreads();
        if (tid < DX) {
            float acc = 0.f;
            #pragma unroll
            for (int aa = 0; aa < DA; ++aa) acc = fmaf(sK[tid][aa], s_r[aa], acc);
            float mt = s_mu[tid] + m * acc;
            s_mut[tid] = mt;
            out[BASE_MT + ((size_t)t * NB + b) * DX + tid] = mt;
        }
        __syncthreads();
        if (tid < DX) {
            float acc = 0.f;
            #pragma unroll
            for (int k = 0; k < DX; ++k) acc = fmaf(sA[tid][k], s_mut[k], acc);
            #pragma unroll
            for (int k = 0; k < DX; ++k) acc = fmaf(sB[tid][k], s_u[k], acc);
            s_mu[tid] = acc;
            out[BASE_MP + ((size_t)t * NB + b) * DX + tid] = acc;
        }
        const bool conv = m1 && (sFlag == 0) && (t >= lastMasked);
        __syncthreads();
        cur = nxt;
        if (conv) { t_frozen = t; break; }
    }

    if (t_frozen < T_STEPS) {
        sPflat[tid]  = sP[cur][i][j];
        sLtflat[tid] = sLt[i][j];
        __syncthreads();
        const int warp = tid >> 5, lane = tid & 31, lr = lane & 15;
        const int t0f = t_frozen + 1;
        const int n = T_STEPS - t0f;
        const int L = (n + 7) / 8;
        const int cs = t0f + warp * L;
        const int ce = min(cs + L, T_STEPS);
        const int tb = (warp == 0) ? t0f : cs - L;
        const float4* pf = (const float4*)sPflat;
        const float4* lf = (const float4*)sLtflat;
        const float4 p0 = pf[2 * lane], p1 = pf[2 * lane + 1];
        const float4 l0 = lf[2 * lane], l1 = lf[2 * lane + 1];
        int tt = t0f + warp;
        float Crow[DX], Krow[DA];
        #pragma unroll
        for (int k = 0; k < DX; ++k) Crow[k] = sC[lane][k];
        #pragma unroll
        for (int aa = 0; aa < DA; ++aa) Krow[aa] = sK[lr][aa];
        float mu = (warp == 0) ? s_mu[lr] : 0.f;
        for (int t = tb; t < ce; ++t) {
            const float m = s_mask[t];
            const float av = __ldg(&ga[((size_t)b * T_STEPS + t) * DA + lane]);
            const float uv = (lane < DX && t < T_STEPS - 1)
                ? __ldg(&gu[((size_t)b * T_STEPS + t) * DX + lane]) : 0.f;
            if (tt < T_STEPS) {
                size_t off = ((size_t)tt * NB + b) * 256 + lane * 8;
                float4* o1 = (float4*)(out + BASE_LP + off);
                o1[0] = p0; o1[1] = p1;
                float4* o2 = (float4*)(out + BASE_LT + off);
                o2[0] = l0; o2[1] = l1;
                tt += 8;
            }
            float ap0 = 0.f, ap1 = 0.f;
            #pragma unroll
            for (int k = 0; k < DX; k += 2) {
                ap0 = fmaf(Crow[k],     __shfl_sync(0xffffffffu, mu, k),     ap0);
                ap1 = fmaf(Crow[k + 1], __shfl_sync(0xffffffffu, mu, k + 1), ap1);
            }
            const float r = fmaf(m, av, -(ap0 + ap1));
            float g0 = 0.f, g1 = 0.f, g2 = 0.f, g3 = 0.f;
            #pragma unroll
            for (int aa = 0; aa < DA; aa += 4) {
                g0 = fmaf(Krow[aa],     __shfl_sync(0xffffffffu, r, aa),     g0);
                g1 = fmaf(Krow[aa + 1], __shfl_sync(0xffffffffu, r, aa + 1), g1);
                g2 = fmaf(Krow[aa + 2], __shfl_sync(0xffffffffu, r, aa + 2), g2);
                g3 = fmaf(Krow[aa + 3], __shfl_sync(0xffffffffu, r, aa + 3), g3);
            }
            const float mt = fmaf(m, (g0 + g1) + (g2 + g3), mu);
            float mun = 0.f;
            #pragma unroll
            for (int k = 0; k < DX; ++k) {
                mun = fmaf(sA[lr][k], __shfl_sync(0xffffffffu, mt, k), mun);
                mun = fmaf(sB[lr][k], __shfl_sync(0xffffffffu, uv, k), mun);
            }
            if (t >= cs && lane < DX) {
                out[BASE_MT + ((size_t)t * NB + b) * DX + lane] = mt;
                out[BASE_MP + ((size_t)t * NB + b) * DX + lane] = mun;
            }
            mu = mun;
        }
        for (; tt < T_STEPS; tt += 8) {
            size_t off = ((size_t)tt * NB + b) * 256 + lane * 8;
            float4* o1 = (float4*)(out + BASE_LP + off);
            o1[0] = p0; o1[1] = p1;
            float4* o2 = (float4*)(out + BASE_LT + off);
            o2[0] = l0; o2[1] = l1;
        }
    }
}

extern "C" void kernel_launch(void* const* d_in, const int* in_sizes, int n_in,
                              void* d_out, int out_size) {
    (void)in_sizes; (void)n_in; (void)out_size;
    const float* ga    = (const float*)d_in[0];
    const float* gu    = (const float*)d_in[1];
    const float* gmask = (const float*)d_in[2];
    const float* gA    = (const float*)d_in[3];
    const float* gB    = (const float*)d_in[4];
    const float* gC    = (const float*)d_in[5];
    const float* gmu0  = (const float*)d_in[6];
    const float* gLam0 = (const float*)d_in[7];
    const float* gWlog = (const float*)d_in[8];
    const float* gRlog = (const float*)d_in[9];
    float* out = (float*)d_out;

    k_scan<<<1024, 256>>>(gmask);
    k1_riccati<<<1, 256>>>(gA, gC, gLam0, gWlog, gRlog);
    k2_dfl<<<NB * 16, 256>>>(ga, gu, gB, out);
    k3_mu<<<NB, 256>>>(gmu0, out);
    ldm_fallback<<<NB, 256>>>(ga, gu, gmask, gA, gB, gC, gmu0, gLam0,
                              gWlog, gRlog, out);
}